// round 13
// baseline (speedup 1.0000x reference)
#include <cuda_runtime.h>
#include <cuda_fp16.h>
#include <cstdint>

typedef unsigned long long u64;
typedef uint32_t u32;

// ---------------- scratch (device globals, no allocations) ----------------
__device__ float g_f [8192*1024];
__device__ float g_r [8192*1024];
__device__ float g_q [8192*1024];
__device__ float g_p [3*8192*64];
__device__ float g_pr[3*8192*64];
__device__ float g_he[8ull*8192*1024];

__device__ __half g_xoh[8192*128],  g_xol[8192*128];
__device__ __half g_h1h[8192*512],  g_h1l[8192*512];
__device__ __half g_h2h[8192*512],  g_h2l[8192*512];
__device__ __half g_fh [8192*1024];
__device__ __half g_xxh[8ull*8192*1024];
__device__ __half g_w1h[512*128];
__device__ __half g_w2h[512*512];
__device__ __half g_w3h[1024*512];
__device__ __half g_weh[16ull*1024*1024];

// ---------------- PTX helpers (family-portable: sm_80+) ----------------
__device__ __forceinline__ u32 smem_u32(const void* p){
  u32 a; asm("{ .reg .u64 t; cvta.to.shared.u64 t, %1; cvt.u32.u64 %0, t; }" : "=r"(a) : "l"(p)); return a;
}
#define CP16(d,s) asm volatile("cp.async.cg.shared.global [%0], [%1], 16;" :: "r"(d), "l"(s) : "memory")
#define CP_COMMIT() asm volatile("cp.async.commit_group;" ::: "memory")
#define CP_WAIT(n)  asm volatile("cp.async.wait_group %0;" :: "n"(n) : "memory")
#define LDSM_X4(r0,r1,r2,r3,a) \
  asm volatile("ldmatrix.sync.aligned.m8n8.x4.shared.b16 {%0,%1,%2,%3}, [%4];" \
    : "=r"(r0),"=r"(r1),"=r"(r2),"=r"(r3) : "r"(a))
#define MMA16816H(c,a0,a1,a2,a3,b0,b1) \
  asm volatile("mma.sync.aligned.m16n8k16.row.col.f32.f16.f16.f32 " \
    "{%0,%1,%2,%3},{%4,%5,%6,%7},{%8,%9},{%0,%1,%2,%3};" \
    : "+f"((c)[0]),"+f"((c)[1]),"+f"((c)[2]),"+f"((c)[3]) \
    : "r"(a0),"r"(a1),"r"(a2),"r"(a3),"r"(b0),"r"(b1))
#define SWZ(o) ((o) ^ (((o) >> 3) & 0x70))

// ---------------- fp16 split (input x only) ----------------
__global__ void cvt_split_k(const float* __restrict__ in, int lda, int cols,
                            __half* __restrict__ hi, __half* __restrict__ lo, long total){
  long idx = ((long)blockIdx.x*256 + threadIdx.x)*4;
  if(idx >= total) return;
  long row = idx / cols; int col = (int)(idx % cols);
  float4 v = *(const float4*)(in + row*lda + col);
  float vv[4] = {v.x, v.y, v.z, v.w};
  __half h[4], l[4];
  #pragma unroll
  for(int j=0;j<4;j++){
    h[j] = __float2half_rn(vv[j]);
    l[j] = __float2half_rn(vv[j] - __half2float(h[j]));
  }
  *(__half2*)(hi+idx)   = __halves2half2(h[0],h[1]);
  *(__half2*)(hi+idx+2) = __halves2half2(h[2],h[3]);
  *(__half2*)(lo+idx)   = __halves2half2(l[0],l[1]);
  *(__half2*)(lo+idx+2) = __halves2half2(l[2],l[3]);
}

// transpose: W[z][Kd][Nd] fp32 -> [z][Nd][Kd] fp16
__global__ void tsp_k(const float* __restrict__ W, __half* __restrict__ Wh, int Kd, int Nd){
  __shared__ float t[32][33];
  long z = blockIdx.z;
  const float* Wz = W + z*(long)Kd*Nd;
  __half* Hz = Wh + z*(long)Kd*Nd;
  int kb = blockIdx.y*32, nb = blockIdx.x*32;
  int tx = threadIdx.x & 31, ty = threadIdx.x >> 5;
  #pragma unroll
  for(int r=0;r<32;r+=8) t[ty+r][tx] = Wz[(long)(kb+ty+r)*Nd + nb+tx];
  __syncthreads();
  #pragma unroll
  for(int r=0;r<32;r+=8)
    Hz[(long)(nb+ty+r)*Kd + kb+tx] = __float2half_rn(t[tx][ty+r]);
}

// ---------------- HMMA GEMM, tile 128x128, BK=64, 4-stage ----
// ATERMS=2: D=(Ah+Al)@Wh^T (stage 48KB).  ATERMS=1: D=Ah@Wh^T (stage 32KB).
// MODE 0: none, 1: relu. WF32: write fp32 C. WSPLIT 0: none, 1: fp16 hi, 2: hi+lo.
template<int ATERMS>
__device__ __forceinline__ void stage_load(u32 sbase,
    const __half* __restrict__ Ah, const __half* __restrict__ Al, int m0, int lda,
    const __half* __restrict__ Wh, int n0, int ldw,
    int k0, int tid){
  #pragma unroll
  for(int t=0;t<4;t++){
    int idx = tid + t*256;
    int row = idx >> 3, c8 = idx & 7;
    u32 sw = SWZ((u32)(row*128 + c8*16));
    long ao = (long)(m0+row)*lda + k0 + c8*8;
    long wo = (long)(n0+row)*ldw + k0 + c8*8;
    CP16(sbase + sw, Ah + ao);
    if(ATERMS == 2){
      CP16(sbase + 16384 + sw, Al + ao);
      CP16(sbase + 32768 + sw, Wh + wo);
    } else {
      CP16(sbase + 16384 + sw, Wh + wo);
    }
  }
}

template<int MODE, bool WF32, int WSPLIT, int ATERMS>
__global__ void __launch_bounds__(256,1) tc_gemm(
    const __half* __restrict__ Ahi, const __half* __restrict__ Alo, long sA, int lda,
    const __half* __restrict__ Whi, long sW,
    const float* __restrict__ bias, long sB,
    float* __restrict__ C,
    __half* __restrict__ Chi, __half* __restrict__ Clo, long sC,
    int N, int K)
{
  constexpr int STG = (ATERMS==2) ? 49152 : 32768;
  constexpr u32 WOFF = (ATERMS==2) ? 32768u : 16384u;
  extern __shared__ char smem[];
  const int tid = threadIdx.x, wid = tid >> 5, lane = tid & 31;
  const long z = blockIdx.z;
  Ahi += z*sA; if(ATERMS==2) Alo += z*sA;
  Whi += z*sW; bias += z*sB;
  if(WF32)       C   += z*sC;
  if(WSPLIT>=1)  Chi += z*sC;
  if(WSPLIT==2)  Clo += z*sC;
  const int m0 = blockIdx.y*128, n0 = blockIdx.x*128;
  const int mrow0 = (wid >> 1)*32, ncol0 = (wid & 1)*64;
  u32 sb = smem_u32(smem);
  float* bias_s = (float*)(smem + 4*STG);
  if(tid < 128) bias_s[tid] = bias[n0+tid];

  const int arow = mrow0 + (lane & 15);
  const u32 akh  = ((lane >> 4) & 1) * 16;
  const int bn   = ncol0 + (lane & 7) + ((lane >> 4) & 1) * 8;
  const u32 bkh  = ((lane >> 3) & 1) * 16;

  float acc[2][8][4];
  #pragma unroll
  for(int a=0;a<2;a++)
    #pragma unroll
    for(int b=0;b<8;b++)
      #pragma unroll
      for(int c=0;c<4;c++) acc[a][b][c]=0.f;

  const int nchunks = K >> 6;
  stage_load<ATERMS>(sb, Ahi, Alo, m0, lda, Whi, n0, K, 0, tid);
  CP_COMMIT();
  if(nchunks > 1){
    stage_load<ATERMS>(sb + STG, Ahi, Alo, m0, lda, Whi, n0, K, 64, tid);
    CP_COMMIT();
  }

  for(int i=0;i<nchunks;i++){
    if(i+2 < nchunks){
      int buf = (i+2)&3;
      stage_load<ATERMS>(sb + buf*STG, Ahi, Alo, m0, lda, Whi, n0, K, (i+2)*64, tid);
      CP_COMMIT();
      CP_WAIT(2);
    } else if(i+1 < nchunks){
      CP_WAIT(1);
    } else {
      CP_WAIT(0);
    }
    __syncthreads();
    u32 sbase = sb + (i&3)*STG;
    #pragma unroll
    for(int k=0;k<4;k++){
      u32 ah[2][4], al[2][4], bh[4][4];
      #pragma unroll
      for(int mt=0;mt<2;mt++){
        u32 sw = SWZ((u32)((arow + mt*16)*128) + k*32 + akh);
        LDSM_X4(ah[mt][0],ah[mt][1],ah[mt][2],ah[mt][3], sbase + sw);
        if(ATERMS == 2){
          LDSM_X4(al[mt][0],al[mt][1],al[mt][2],al[mt][3], sbase + 16384 + sw);
        }
      }
      #pragma unroll
      for(int ng=0;ng<4;ng++){
        u32 sw = SWZ((u32)((bn + ng*16)*128) + k*32 + bkh);
        LDSM_X4(bh[ng][0],bh[ng][1],bh[ng][2],bh[ng][3], sbase + WOFF + sw);
      }
      #pragma unroll
      for(int ng=0;ng<4;ng++)
        #pragma unroll
        for(int mt=0;mt<2;mt++){
          MMA16816H(acc[mt][ng*2+0], ah[mt][0],ah[mt][1],ah[mt][2],ah[mt][3], bh[ng][0],bh[ng][1]);
          MMA16816H(acc[mt][ng*2+1], ah[mt][0],ah[mt][1],ah[mt][2],ah[mt][3], bh[ng][2],bh[ng][3]);
        }
      if(ATERMS == 2){
        #pragma unroll
        for(int ng=0;ng<4;ng++)
          #pragma unroll
          for(int mt=0;mt<2;mt++){
            MMA16816H(acc[mt][ng*2+0], al[mt][0],al[mt][1],al[mt][2],al[mt][3], bh[ng][0],bh[ng][1]);
            MMA16816H(acc[mt][ng*2+1], al[mt][0],al[mt][1],al[mt][2],al[mt][3], bh[ng][2],bh[ng][3]);
          }
      }
    }
    // no trailing barrier: 4-stage ring guarantees no WAR hazard
  }

  #pragma unroll
  for(int mt=0;mt<2;mt++){
    const long r0 = m0 + mrow0 + mt*16 + (lane >> 2);
    #pragma unroll
    for(int nt=0;nt<8;nt++){
      const int lc = ncol0 + nt*8 + (lane & 3)*2;
      const float b0 = bias_s[lc], b1 = bias_s[lc+1];
      float v0 = acc[mt][nt][0]+b0, v1 = acc[mt][nt][1]+b1;
      float v2 = acc[mt][nt][2]+b0, v3 = acc[mt][nt][3]+b1;
      if(MODE == 1){
        v0=fmaxf(v0,0.f); v1=fmaxf(v1,0.f); v2=fmaxf(v2,0.f); v3=fmaxf(v3,0.f);
      }
      const long o0 = r0*(long)N + n0 + lc, o1 = (r0+8)*(long)N + n0 + lc;
      if(WF32){
        *(float2*)&C[o0] = make_float2(v0,v1);
        *(float2*)&C[o1] = make_float2(v2,v3);
      }
      if(WSPLIT >= 1){
        __half h0=__float2half_rn(v0), h1=__float2half_rn(v1);
        __half h2=__float2half_rn(v2), h3=__float2half_rn(v3);
        *(__half2*)&Chi[o0] = __halves2half2(h0,h1);
        *(__half2*)&Chi[o1] = __halves2half2(h2,h3);
        if(WSPLIT == 2){
          *(__half2*)&Clo[o0] = __halves2half2(
              __float2half_rn(v0-__half2float(h0)), __float2half_rn(v1-__half2float(h1)));
          *(__half2*)&Clo[o1] = __halves2half2(
              __float2half_rn(v2-__half2float(h2)), __float2half_rn(v3-__half2float(h3)));
        }
      }
    }
  }
}

// ---------------- f32x2 SGEMM (gate + routing) ----------------
__device__ __forceinline__ u64 pk2(float lo, float hi){
  u64 r; asm("mov.b64 %0, {%1, %2};" : "=l"(r) : "f"(lo), "f"(hi)); return r;
}
__device__ __forceinline__ void fma2(u64 &d, u64 a, u64 b){
  asm("fma.rn.f32x2 %0, %1, %2, %0;" : "+l"(d) : "l"(a), "l"(b));
}
__device__ __forceinline__ float2 upk(u64 v){
  float2 f; asm("mov.b64 {%0, %1}, %2;" : "=f"(f.x), "=f"(f.y) : "l"(v)); return f;
}

template<int BM, int BN, int MODE, bool RELUA>
__global__ void __launch_bounds__(256, (BM==64?3:2)) gemm_k(
    const float* __restrict__ A, int lda, long sA,
    const float* __restrict__ W, long sW,
    const float* __restrict__ bias, long sB,
    const float* __restrict__ mul,
    float* __restrict__ C, long sC,
    int M, int N, int K)
{
  constexpr int BK=16, TN=BN/16, TM=BM/16;
  __shared__ float As[BK][BM];
  __shared__ float Ws[BK][BN];
  const int z = blockIdx.z;
  A += (long)z*sA; W += (long)z*sW; bias += (long)z*sB; C += (long)z*sC;
  const int m0 = blockIdx.y*BM;
  const int n0 = blockIdx.x*BN;
  const int tid = threadIdx.x;
  const int tx = tid & 15, ty = tid >> 4;

  u64 acc[TM][TN/2];
  #pragma unroll
  for(int i=0;i<TM;i++)
    #pragma unroll
    for(int j=0;j<TN/2;j++) acc[i][j]=0ull;

  for(int k0=0;k0<K;k0+=BK){
    #pragma unroll
    for(int idx4=tid; idx4 < BM*4; idx4+=256){
      int row = idx4 >> 2;
      int c4  = (idx4 & 3)*4;
      float4 v = *(const float4*)(A + (long)(m0+row)*lda + k0 + c4);
      if(RELUA){ v.x=fmaxf(v.x,0.f); v.y=fmaxf(v.y,0.f); v.z=fmaxf(v.z,0.f); v.w=fmaxf(v.w,0.f); }
      As[c4+0][row]=v.x; As[c4+1][row]=v.y; As[c4+2][row]=v.z; As[c4+3][row]=v.w;
    }
    #pragma unroll
    for(int idx=tid; idx < BK*BN/4; idx+=256){
      int row = idx / (BN/4);
      int c4  = (idx % (BN/4))*4;
      *(float4*)&Ws[row][c4] = *(const float4*)(W + (long)(k0+row)*N + n0 + c4);
    }
    __syncthreads();
    #pragma unroll
    for(int kk=0;kk<BK;kk++){
      u64 ap[TM];
      #pragma unroll
      for(int j=0;j<TM/4;j++){
        float4 a0 = *(const float4*)&As[kk][ty*TM + j*4];
        ap[j*4+0]=pk2(a0.x,a0.x); ap[j*4+1]=pk2(a0.y,a0.y);
        ap[j*4+2]=pk2(a0.z,a0.z); ap[j*4+3]=pk2(a0.w,a0.w);
      }
      u64 wp[TN/2];
      #pragma unroll
      for(int j=0;j<TN/4;j++){
        float4 w0 = *(const float4*)&Ws[kk][tx*TN + j*4];
        wp[j*2+0]=pk2(w0.x,w0.y); wp[j*2+1]=pk2(w0.z,w0.w);
      }
      #pragma unroll
      for(int m=0;m<TM;m++)
        #pragma unroll
        for(int j=0;j<TN/2;j++)
          fma2(acc[m][j], ap[m], wp[j]);
    }
    __syncthreads();
  }

  const int col = n0 + tx*TN;
  float bv[TN];
  #pragma unroll
  for(int n=0;n<TN;n++) bv[n]=bias[col+n];

  #pragma unroll
  for(int m=0;m<TM;m++){
    const long row = m0 + ty*TM + m;
    const long base = row*(long)N + col;
    float o[TN];
    #pragma unroll
    for(int j=0;j<TN/2;j++){ float2 f=upk(acc[m][j]); o[2*j]=f.x+bv[2*j]; o[2*j+1]=f.y+bv[2*j+1]; }
    if constexpr (MODE==1){
      #pragma unroll
      for(int n=0;n<TN;n++) o[n]=fmaxf(o[n],0.f);
    } else if constexpr (MODE==2){
      #pragma unroll
      for(int n=0;n<TN;n++) o[n]=fmaxf(o[n],0.f)*mul[base+n];
    } else if constexpr (MODE==3){
      #pragma unroll
      for(int n=0;n<TN;n++) o[n]=fmaxf(o[n]*mul[base+n],0.f);
    }
    #pragma unroll
    for(int j=0;j<TN/4;j++)
      *(float4*)&C[base + 4*j] = make_float4(o[4*j],o[4*j+1],o[4*j+2],o[4*j+3]);
  }
}

// ---------------- softmax over last dim ----------------
__global__ void softmax_k(const float* __restrict__ p, float* __restrict__ out, int nrows){
  int idx = blockIdx.x*256 + threadIdx.x;
  if(idx >= nrows) return;
  float4 v0 = *(const float4*)(p + (long)idx*8);
  float4 v1 = *(const float4*)(p + (long)idx*8 + 4);
  float v[8]={v0.x,v0.y,v0.z,v0.w,v1.x,v1.y,v1.z,v1.w};
  float m=v[0];
  #pragma unroll
  for(int j=1;j<8;j++) m=fmaxf(m,v[j]);
  float s=0.f;
  #pragma unroll
  for(int j=0;j<8;j++){ v[j]=expf(v[j]-m); s+=v[j]; }
  float inv=1.f/s;
  #pragma unroll
  for(int j=0;j<8;j++) v[j]*=inv;
  *(float4*)(out + (long)idx*8)   = make_float4(v[0],v[1],v[2],v[3]);
  *(float4*)(out + (long)idx*8+4) = make_float4(v[4],v[5],v[6],v[7]);
}

// ---------------- mix layer0 -> fp16 (1-term) ----------------
__global__ void mix_k(const float* __restrict__ he, const float* __restrict__ probs,
                      __half* __restrict__ xh){
  const int b = blockIdx.x;
  __shared__ float p[64];
  if(threadIdx.x<64) p[threadIdx.x]=probs[b*64+threadIdx.x];
  __syncthreads();
  const int d = threadIdx.x*4;
  float4 h[8];
  #pragma unroll
  for(int j=0;j<8;j++) h[j]=*(const float4*)(he + ((long)j*8192+b)*1024 + d);
  #pragma unroll
  for(int i=0;i<8;i++){
    float4 a=make_float4(0.f,0.f,0.f,0.f);
    #pragma unroll
    for(int j=0;j<8;j++){
      float w=p[i*8+j];
      a.x+=w*h[j].x; a.y+=w*h[j].y; a.z+=w*h[j].z; a.w+=w*h[j].w;
    }
    const long base = ((long)i*8192+b)*1024 + d;
    *(__half2*)(xh+base)   = __halves2half2(__float2half_rn(a.x),__float2half_rn(a.y));
    *(__half2*)(xh+base+2) = __halves2half2(__float2half_rn(a.z),__float2half_rn(a.w));
  }
}

// ---------------- fused mix(layer1) + heads ----------------
__global__ void heads_mix_k(const float* __restrict__ he, const float* __restrict__ probs,
                            const float* __restrict__ aW, const float* __restrict__ ab,
                            const float* __restrict__ cW, const float* __restrict__ cb,
                            float* __restrict__ out){
  const int b=blockIdx.x, tid=threadIdx.x, lane=tid&31, wid=tid>>5;
  __shared__ float p[64];
  if(tid<64) p[tid]=probs[b*64+tid];
  __syncthreads();
  const int d = tid*4;
  float4 h[8];
  #pragma unroll
  for(int j=0;j<8;j++) h[j]=*(const float4*)(he + ((long)j*8192+b)*1024 + d);

  float acc[9];
  #pragma unroll
  for(int o=0;o<9;o++) acc[o]=0.f;
  #pragma unroll
  for(int e=0;e<8;e++){
    float4 xv=make_float4(0.f,0.f,0.f,0.f);
    #pragma unroll
    for(int j=0;j<8;j++){
      float w=p[e*8+j];
      xv.x+=w*h[j].x; xv.y+=w*h[j].y; xv.z+=w*h[j].z; xv.w+=w*h[j].w;
    }
    const float* aw = aW + ((long)e*1024 + d)*8;
    const float* cw = cW + (long)e*1024 + d;
    float vv[4]={xv.x,xv.y,xv.z,xv.w};
    #pragma unroll
    for(int c=0;c<4;c++){
      float4 w0=*(const float4*)(aw + c*8);
      float4 w1=*(const float4*)(aw + c*8+4);
      float v=vv[c];
      acc[0]+=v*w0.x; acc[1]+=v*w0.y; acc[2]+=v*w0.z; acc[3]+=v*w0.w;
      acc[4]+=v*w1.x; acc[5]+=v*w1.y; acc[6]+=v*w1.z; acc[7]+=v*w1.w;
      acc[8]+=v*cw[c];
    }
  }
  #pragma unroll
  for(int o=0;o<9;o++){
    #pragma unroll
    for(int s=16;s>0;s>>=1) acc[o] += __shfl_down_sync(0xffffffffu, acc[o], s);
  }
  __shared__ float red[8][9];
  if(lane==0){
    #pragma unroll
    for(int o=0;o<9;o++) red[wid][o]=acc[o];
  }
  __syncthreads();
  if(tid<9){
    float s=0.f;
    #pragma unroll
    for(int w=0;w<8;w++) s+=red[w][tid];
    float bs=0.f;
    if(tid<8){ for(int e=0;e<8;e++) bs+=ab[e*8+tid]; out[(long)b*8+tid]=s+bs; }
    else     { for(int e=0;e<8;e++) bs+=cb[e];       out[65536+b]=s+bs; }
  }
}

// ---------------- launch ----------------
extern "C" void kernel_launch(void* const* d_in, const int* in_sizes, int n_in,
                              void* d_out, int out_size)
{
  const float* x    = (const float*)d_in[0];
  const float* sW1  = (const float*)d_in[1];
  const float* sb1  = (const float*)d_in[2];
  const float* sW2  = (const float*)d_in[3];
  const float* sb2  = (const float*)d_in[4];
  const float* sW3  = (const float*)d_in[5];
  const float* sb3  = (const float*)d_in[6];
  const float* tW   = (const float*)d_in[7];
  const float* tb   = (const float*)d_in[8];
  const float* rdW  = (const float*)d_in[9];
  const float* rdb  = (const float*)d_in[10];
  const float* ruW  = (const float*)d_in[11];
  const float* rub  = (const float*)d_in[12];
  const float* eW   = (const float*)d_in[13];
  const float* eb   = (const float*)d_in[14];
  const float* aW   = (const float*)d_in[15];
  const float* ab   = (const float*)d_in[16];
  const float* cW   = (const float*)d_in[17];
  const float* cb   = (const float*)d_in[18];
  float* out = (float*)d_out;

  float *f,*r,*q,*p,*pr,*he;
  cudaGetSymbolAddress((void**)&f , g_f );
  cudaGetSymbolAddress((void**)&r , g_r );
  cudaGetSymbolAddress((void**)&q , g_q );
  cudaGetSymbolAddress((void**)&p , g_p );
  cudaGetSymbolAddress((void**)&pr, g_pr);
  cudaGetSymbolAddress((void**)&he, g_he);

  __half *xoh,*xol,*h1h,*h1l,*h2h,*h2l,*fh,*xxh;
  __half *w1h,*w2h,*w3h,*weh;
  cudaGetSymbolAddress((void**)&xoh, g_xoh); cudaGetSymbolAddress((void**)&xol, g_xol);
  cudaGetSymbolAddress((void**)&h1h, g_h1h); cudaGetSymbolAddress((void**)&h1l, g_h1l);
  cudaGetSymbolAddress((void**)&h2h, g_h2h); cudaGetSymbolAddress((void**)&h2l, g_h2l);
  cudaGetSymbolAddress((void**)&fh , g_fh );
  cudaGetSymbolAddress((void**)&xxh, g_xxh);
  cudaGetSymbolAddress((void**)&w1h, g_w1h);
  cudaGetSymbolAddress((void**)&w2h, g_w2h);
  cudaGetSymbolAddress((void**)&w3h, g_w3h);
  cudaGetSymbolAddress((void**)&weh, g_weh);

  constexpr int SMEM_T2 = 4*49152 + 1024;   // ATERMS=2 stages
  constexpr int SMEM_T1 = 4*32768 + 1024;   // ATERMS=1 stages
  cudaFuncSetAttribute(tc_gemm<1,false,2,2>, cudaFuncAttributeMaxDynamicSharedMemorySize, SMEM_T2);
  cudaFuncSetAttribute(tc_gemm<0,true ,1,2>, cudaFuncAttributeMaxDynamicSharedMemorySize, SMEM_T2);
  cudaFuncSetAttribute(tc_gemm<1,true ,0,1>, cudaFuncAttributeMaxDynamicSharedMemorySize, SMEM_T1);

  cudaStream_t s2;
  cudaStreamCreateWithFlags(&s2, cudaStreamNonBlocking);
  cudaEvent_t eFork, eWts, eTrunk, eRoute;
  cudaEventCreateWithFlags(&eFork,  cudaEventDisableTiming);
  cudaEventCreateWithFlags(&eWts,   cudaEventDisableTiming);
  cudaEventCreateWithFlags(&eTrunk, cudaEventDisableTiming);
  cudaEventCreateWithFlags(&eRoute, cudaEventDisableTiming);

  dim3 blk(256);

  // ---- fork: expert-weight prep on s2, overlapped with trunk ----
  cudaEventRecord(eFork, 0);
  cudaStreamWaitEvent(s2, eFork, 0);
  tsp_k<<<dim3(32,32,16),blk,0,s2>>>(eW, weh, 1024, 1024);
  cudaEventRecord(eWts, s2);

  // ---- main: trunk weight prep + trunk GEMMs (fp16 2-term A) ----
  tsp_k<<<dim3(16, 4, 1),blk>>>(sW1, w1h, 128, 512);
  tsp_k<<<dim3(16,16, 1),blk>>>(sW2, w2h, 512, 512);
  tsp_k<<<dim3(32,16, 1),blk>>>(sW3, w3h, 512, 1024);
  cvt_split_k<<<1024,blk>>>(x, 192, 128, xoh, xol, 8192L*128);
  tc_gemm<1,false,2,2><<<dim3(4,64,1),blk,SMEM_T2>>>(
      xoh,xol,0,128, w1h,0, sb1,0, nullptr, h1h,h1l,0, 512,128);
  tc_gemm<1,false,2,2><<<dim3(4,64,1),blk,SMEM_T2>>>(
      h1h,h1l,0,512, w2h,0, sb2,0, nullptr, h2h,h2l,0, 512,512);
  tc_gemm<0,true,1,2><<<dim3(8,64,1),blk,SMEM_T2>>>(
      h2h,h2l,0,512, w3h,0, sb3,0, f, fh,nullptr,0, 1024,512);
  cudaEventRecord(eTrunk, 0);

  // ---- s2: routing chain (fma pipe), overlapped with expert L0 GEMM ----
  cudaStreamWaitEvent(s2, eTrunk, 0);
  gemm_k<128,128,2,false><<<dim3(8,64,1),blk,0,s2>>>(x+128,192,0, tW,0, tb,0, f, r,0, 8192,1024,64);
  gemm_k<64,64,0,true ><<<dim3(1,128,1),blk,0,s2>>>(r,1024,0, rdW,0, rdb,0, nullptr, p,0, 8192,64,1024);
  gemm_k<128,128,3,false><<<dim3(8,64,1),blk,0,s2>>>(p,64,0,
      ruW,0, rub,0, r, q,0, 8192,1024,64);
  gemm_k<64,64,0,false><<<dim3(1,128,1),blk,0,s2>>>(q,1024,0,
      rdW+1024L*64,0, rdb+64,0, nullptr, p+8192L*64,0, 8192,64,1024);
  softmax_k<<<(2*8192*8+255)/256,blk,0,s2>>>(p, pr, 2*8192*8);
  cudaEventRecord(eRoute, s2);

  // ---- main: expert layer 0 (fp16 1-term A), concurrent with routing ----
  cudaStreamWaitEvent(0, eWts, 0);
  tc_gemm<1,true,0,1><<<dim3(8,64,8),blk,SMEM_T1>>>(
      fh,nullptr,0,1024, weh,1048576, eb,1024, he, nullptr,nullptr,8388608, 1024,1024);

  // ---- join: mixing needs routing probs ----
  cudaStreamWaitEvent(0, eRoute, 0);
  mix_k<<<8192,blk>>>(he, pr, xxh);

  // expert layer 1 (fp16 1-term A)
  tc_gemm<1,true,0,1><<<dim3(8,64,8),blk,SMEM_T1>>>(
      xxh,nullptr,8388608,1024, weh+8L*1048576,1048576, eb+8192,1024,
      he, nullptr,nullptr,8388608, 1024,1024);

  // fused mix(layer1) + heads
  heads_mix_k<<<8192,blk>>>(he, pr+8192*64, aW, ab, cW, cb, out);
}

// round 14
// speedup vs baseline: 1.5389x; 1.5389x over previous
#include <cuda_runtime.h>
#include <cuda_fp16.h>
#include <cstdint>

typedef unsigned long long u64;
typedef uint32_t u32;

// ---------------- scratch (device globals, no allocations) ----------------
__device__ float g_f [8192*1024];
__device__ float g_r [8192*1024];
__device__ float g_q [8192*1024];
__device__ float g_p [3*8192*64];
__device__ float g_pr[3*8192*64];
__device__ float g_he[8ull*8192*1024];

__device__ __half g_xoh[8192*128],  g_xol[8192*128];
__device__ __half g_h1h[8192*512],  g_h1l[8192*512];
__device__ __half g_h2h[8192*512],  g_h2l[8192*512];
__device__ __half g_fh [8192*1024];
__device__ __half g_xxh[8ull*8192*1024];
__device__ __half g_w1h[512*128];
__device__ __half g_w2h[512*512];
__device__ __half g_w3h[1024*512];
__device__ __half g_weh[16ull*1024*1024];

// ---------------- PTX helpers (family-portable: sm_80+) ----------------
__device__ __forceinline__ u32 smem_u32(const void* p){
  u32 a; asm("{ .reg .u64 t; cvta.to.shared.u64 t, %1; cvt.u32.u64 %0, t; }" : "=r"(a) : "l"(p)); return a;
}
#define CP16(d,s) asm volatile("cp.async.cg.shared.global [%0], [%1], 16;" :: "r"(d), "l"(s) : "memory")
#define CP_COMMIT() asm volatile("cp.async.commit_group;" ::: "memory")
#define CP_WAIT(n)  asm volatile("cp.async.wait_group %0;" :: "n"(n) : "memory")
#define LDSM_X4(r0,r1,r2,r3,a) \
  asm volatile("ldmatrix.sync.aligned.m8n8.x4.shared.b16 {%0,%1,%2,%3}, [%4];" \
    : "=r"(r0),"=r"(r1),"=r"(r2),"=r"(r3) : "r"(a))
#define MMA16816H(c,a0,a1,a2,a3,b0,b1) \
  asm volatile("mma.sync.aligned.m16n8k16.row.col.f32.f16.f16.f32 " \
    "{%0,%1,%2,%3},{%4,%5,%6,%7},{%8,%9},{%0,%1,%2,%3};" \
    : "+f"((c)[0]),"+f"((c)[1]),"+f"((c)[2]),"+f"((c)[3]) \
    : "r"(a0),"r"(a1),"r"(a2),"r"(a3),"r"(b0),"r"(b1))
#define SWZ(o) ((o) ^ (((o) >> 3) & 0x70))

// ---------------- fp16 split (input x only) ----------------
__global__ void cvt_split_k(const float* __restrict__ in, int lda, int cols,
                            __half* __restrict__ hi, __half* __restrict__ lo, long total){
  long idx = ((long)blockIdx.x*256 + threadIdx.x)*4;
  if(idx >= total) return;
  long row = idx / cols; int col = (int)(idx % cols);
  float4 v = *(const float4*)(in + row*lda + col);
  float vv[4] = {v.x, v.y, v.z, v.w};
  __half h[4], l[4];
  #pragma unroll
  for(int j=0;j<4;j++){
    h[j] = __float2half_rn(vv[j]);
    l[j] = __float2half_rn(vv[j] - __half2float(h[j]));
  }
  *(__half2*)(hi+idx)   = __halves2half2(h[0],h[1]);
  *(__half2*)(hi+idx+2) = __halves2half2(h[2],h[3]);
  *(__half2*)(lo+idx)   = __halves2half2(l[0],l[1]);
  *(__half2*)(lo+idx+2) = __halves2half2(l[2],l[3]);
}

// transpose: W[z][Kd][Nd] fp32 -> [z][Nd][Kd] fp16
__global__ void tsp_k(const float* __restrict__ W, __half* __restrict__ Wh, int Kd, int Nd){
  __shared__ float t[32][33];
  long z = blockIdx.z;
  const float* Wz = W + z*(long)Kd*Nd;
  __half* Hz = Wh + z*(long)Kd*Nd;
  int kb = blockIdx.y*32, nb = blockIdx.x*32;
  int tx = threadIdx.x & 31, ty = threadIdx.x >> 5;
  #pragma unroll
  for(int r=0;r<32;r+=8) t[ty+r][tx] = Wz[(long)(kb+ty+r)*Nd + nb+tx];
  __syncthreads();
  #pragma unroll
  for(int r=0;r<32;r+=8)
    Hz[(long)(nb+ty+r)*Kd + kb+tx] = __float2half_rn(t[tx][ty+r]);
}

// ---------------- HMMA GEMM, tile 128x128, BK=64 ----
// ATERMS=2: D=(Ah+Al)@Wh^T, 4 stages x 48KB, prefetch distance 2.
// ATERMS=1: D=Ah@Wh^T,      6 stages x 32KB, prefetch distance 4 (deeper lead
//           time to cover load-completion latency; chunks are half as long).
template<int ATERMS>
__device__ __forceinline__ void stage_load(u32 sbase,
    const __half* __restrict__ Ah, const __half* __restrict__ Al, int m0, int lda,
    const __half* __restrict__ Wh, int n0, int ldw,
    int k0, int tid){
  #pragma unroll
  for(int t=0;t<4;t++){
    int idx = tid + t*256;
    int row = idx >> 3, c8 = idx & 7;
    u32 sw = SWZ((u32)(row*128 + c8*16));
    long ao = (long)(m0+row)*lda + k0 + c8*8;
    long wo = (long)(n0+row)*ldw + k0 + c8*8;
    CP16(sbase + sw, Ah + ao);
    if(ATERMS == 2){
      CP16(sbase + 16384 + sw, Al + ao);
      CP16(sbase + 32768 + sw, Wh + wo);
    } else {
      CP16(sbase + 16384 + sw, Wh + wo);
    }
  }
}

template<int MODE, bool WF32, int WSPLIT, int ATERMS>
__global__ void __launch_bounds__(256,1) tc_gemm(
    const __half* __restrict__ Ahi, const __half* __restrict__ Alo, long sA, int lda,
    const __half* __restrict__ Whi, long sW,
    const float* __restrict__ bias, long sB,
    float* __restrict__ C,
    __half* __restrict__ Chi, __half* __restrict__ Clo, long sC,
    int N, int K)
{
  constexpr int STG  = (ATERMS==2) ? 49152 : 32768;
  constexpr u32 WOFF = (ATERMS==2) ? 32768u : 16384u;
  constexpr int NSTG = (ATERMS==2) ? 4 : 6;
  constexpr int DIST = (ATERMS==2) ? 2 : 4;
  extern __shared__ char smem[];
  const int tid = threadIdx.x, wid = tid >> 5, lane = tid & 31;
  const long z = blockIdx.z;
  Ahi += z*sA; if(ATERMS==2) Alo += z*sA;
  Whi += z*sW; bias += z*sB;
  if(WF32)       C   += z*sC;
  if(WSPLIT>=1)  Chi += z*sC;
  if(WSPLIT==2)  Clo += z*sC;
  const int m0 = blockIdx.y*128, n0 = blockIdx.x*128;
  const int mrow0 = (wid >> 1)*32, ncol0 = (wid & 1)*64;
  u32 sb = smem_u32(smem);
  float* bias_s = (float*)(smem + NSTG*STG);
  if(tid < 128) bias_s[tid] = bias[n0+tid];

  const int arow = mrow0 + (lane & 15);
  const u32 akh  = ((lane >> 4) & 1) * 16;
  const int bn   = ncol0 + (lane & 7) + ((lane >> 4) & 1) * 8;
  const u32 bkh  = ((lane >> 3) & 1) * 16;

  float acc[2][8][4];
  #pragma unroll
  for(int a=0;a<2;a++)
    #pragma unroll
    for(int b=0;b<8;b++)
      #pragma unroll
      for(int c=0;c<4;c++) acc[a][b][c]=0.f;

  const int nchunks = K >> 6;
  const int pre = (DIST < nchunks) ? DIST : nchunks;
  for(int j=0;j<pre;j++){
    stage_load<ATERMS>(sb + j*STG, Ahi, Alo, m0, lda, Whi, n0, K, j*64, tid);
    CP_COMMIT();
  }

  int wbuf = pre % NSTG, rbuf = 0;
  for(int i=0;i<nchunks;i++){
    if(i+DIST < nchunks){
      stage_load<ATERMS>(sb + wbuf*STG, Ahi, Alo, m0, lda, Whi, n0, K, (i+DIST)*64, tid);
      CP_COMMIT();
      wbuf = (wbuf+1 == NSTG) ? 0 : wbuf+1;
      CP_WAIT(DIST);
    } else {
      int rem = nchunks-1-i;   // outstanding groups to keep
      if(DIST==4){
        if(rem>=3)      CP_WAIT(3);
        else if(rem==2) CP_WAIT(2);
        else if(rem==1) CP_WAIT(1);
        else            CP_WAIT(0);
      } else {
        if(rem>=1)      CP_WAIT(1);
        else            CP_WAIT(0);
      }
    }
    __syncthreads();
    u32 sbase = sb + rbuf*STG;
    rbuf = (rbuf+1 == NSTG) ? 0 : rbuf+1;
    #pragma unroll
    for(int k=0;k<4;k++){
      u32 ah[2][4], al[2][4], bh[4][4];
      #pragma unroll
      for(int mt=0;mt<2;mt++){
        u32 sw = SWZ((u32)((arow + mt*16)*128) + k*32 + akh);
        LDSM_X4(ah[mt][0],ah[mt][1],ah[mt][2],ah[mt][3], sbase + sw);
        if(ATERMS == 2){
          LDSM_X4(al[mt][0],al[mt][1],al[mt][2],al[mt][3], sbase + 16384 + sw);
        }
      }
      #pragma unroll
      for(int ng=0;ng<4;ng++){
        u32 sw = SWZ((u32)((bn + ng*16)*128) + k*32 + bkh);
        LDSM_X4(bh[ng][0],bh[ng][1],bh[ng][2],bh[ng][3], sbase + WOFF + sw);
      }
      #pragma unroll
      for(int ng=0;ng<4;ng++)
        #pragma unroll
        for(int mt=0;mt<2;mt++){
          MMA16816H(acc[mt][ng*2+0], ah[mt][0],ah[mt][1],ah[mt][2],ah[mt][3], bh[ng][0],bh[ng][1]);
          MMA16816H(acc[mt][ng*2+1], ah[mt][0],ah[mt][1],ah[mt][2],ah[mt][3], bh[ng][2],bh[ng][3]);
        }
      if(ATERMS == 2){
        #pragma unroll
        for(int ng=0;ng<4;ng++)
          #pragma unroll
          for(int mt=0;mt<2;mt++){
            MMA16816H(acc[mt][ng*2+0], al[mt][0],al[mt][1],al[mt][2],al[mt][3], bh[ng][0],bh[ng][1]);
            MMA16816H(acc[mt][ng*2+1], al[mt][0],al[mt][1],al[mt][2],al[mt][3], bh[ng][2],bh[ng][3]);
          }
      }
    }
    // no trailing barrier: ring distance guarantees no WAR hazard
  }

  #pragma unroll
  for(int mt=0;mt<2;mt++){
    const long r0 = m0 + mrow0 + mt*16 + (lane >> 2);
    #pragma unroll
    for(int nt=0;nt<8;nt++){
      const int lc = ncol0 + nt*8 + (lane & 3)*2;
      const float b0 = bias_s[lc], b1 = bias_s[lc+1];
      float v0 = acc[mt][nt][0]+b0, v1 = acc[mt][nt][1]+b1;
      float v2 = acc[mt][nt][2]+b0, v3 = acc[mt][nt][3]+b1;
      if(MODE == 1){
        v0=fmaxf(v0,0.f); v1=fmaxf(v1,0.f); v2=fmaxf(v2,0.f); v3=fmaxf(v3,0.f);
      }
      const long o0 = r0*(long)N + n0 + lc, o1 = (r0+8)*(long)N + n0 + lc;
      if(WF32){
        *(float2*)&C[o0] = make_float2(v0,v1);
        *(float2*)&C[o1] = make_float2(v2,v3);
      }
      if(WSPLIT >= 1){
        __half h0=__float2half_rn(v0), h1=__float2half_rn(v1);
        __half h2=__float2half_rn(v2), h3=__float2half_rn(v3);
        *(__half2*)&Chi[o0] = __halves2half2(h0,h1);
        *(__half2*)&Chi[o1] = __halves2half2(h2,h3);
        if(WSPLIT == 2){
          *(__half2*)&Clo[o0] = __halves2half2(
              __float2half_rn(v0-__half2float(h0)), __float2half_rn(v1-__half2float(h1)));
          *(__half2*)&Clo[o1] = __halves2half2(
              __float2half_rn(v2-__half2float(h2)), __float2half_rn(v3-__half2float(h3)));
        }
      }
    }
  }
}

// ---------------- f32x2 SGEMM (gate + routing) ----------------
__device__ __forceinline__ u64 pk2(float lo, float hi){
  u64 r; asm("mov.b64 %0, {%1, %2};" : "=l"(r) : "f"(lo), "f"(hi)); return r;
}
__device__ __forceinline__ void fma2(u64 &d, u64 a, u64 b){
  asm("fma.rn.f32x2 %0, %1, %2, %0;" : "+l"(d) : "l"(a), "l"(b));
}
__device__ __forceinline__ float2 upk(u64 v){
  float2 f; asm("mov.b64 {%0, %1}, %2;" : "=f"(f.x), "=f"(f.y) : "l"(v)); return f;
}

template<int BM, int BN, int MODE, bool RELUA>
__global__ void __launch_bounds__(256, (BM==64?3:2)) gemm_k(
    const float* __restrict__ A, int lda, long sA,
    const float* __restrict__ W, long sW,
    const float* __restrict__ bias, long sB,
    const float* __restrict__ mul,
    float* __restrict__ C, long sC,
    int M, int N, int K)
{
  constexpr int BK=16, TN=BN/16, TM=BM/16;
  __shared__ float As[BK][BM];
  __shared__ float Ws[BK][BN];
  const int z = blockIdx.z;
  A += (long)z*sA; W += (long)z*sW; bias += (long)z*sB; C += (long)z*sC;
  const int m0 = blockIdx.y*BM;
  const int n0 = blockIdx.x*BN;
  const int tid = threadIdx.x;
  const int tx = tid & 15, ty = tid >> 4;

  u64 acc[TM][TN/2];
  #pragma unroll
  for(int i=0;i<TM;i++)
    #pragma unroll
    for(int j=0;j<TN/2;j++) acc[i][j]=0ull;

  for(int k0=0;k0<K;k0+=BK){
    #pragma unroll
    for(int idx4=tid; idx4 < BM*4; idx4+=256){
      int row = idx4 >> 2;
      int c4  = (idx4 & 3)*4;
      float4 v = *(const float4*)(A + (long)(m0+row)*lda + k0 + c4);
      if(RELUA){ v.x=fmaxf(v.x,0.f); v.y=fmaxf(v.y,0.f); v.z=fmaxf(v.z,0.f); v.w=fmaxf(v.w,0.f); }
      As[c4+0][row]=v.x; As[c4+1][row]=v.y; As[c4+2][row]=v.z; As[c4+3][row]=v.w;
    }
    #pragma unroll
    for(int idx=tid; idx < BK*BN/4; idx+=256){
      int row = idx / (BN/4);
      int c4  = (idx % (BN/4))*4;
      *(float4*)&Ws[row][c4] = *(const float4*)(W + (long)(k0+row)*N + n0 + c4);
    }
    __syncthreads();
    #pragma unroll
    for(int kk=0;kk<BK;kk++){
      u64 ap[TM];
      #pragma unroll
      for(int j=0;j<TM/4;j++){
        float4 a0 = *(const float4*)&As[kk][ty*TM + j*4];
        ap[j*4+0]=pk2(a0.x,a0.x); ap[j*4+1]=pk2(a0.y,a0.y);
        ap[j*4+2]=pk2(a0.z,a0.z); ap[j*4+3]=pk2(a0.w,a0.w);
      }
      u64 wp[TN/2];
      #pragma unroll
      for(int j=0;j<TN/4;j++){
        float4 w0 = *(const float4*)&Ws[kk][tx*TN + j*4];
        wp[j*2+0]=pk2(w0.x,w0.y); wp[j*2+1]=pk2(w0.z,w0.w);
      }
      #pragma unroll
      for(int m=0;m<TM;m++)
        #pragma unroll
        for(int j=0;j<TN/2;j++)
          fma2(acc[m][j], ap[m], wp[j]);
    }
    __syncthreads();
  }

  const int col = n0 + tx*TN;
  float bv[TN];
  #pragma unroll
  for(int n=0;n<TN;n++) bv[n]=bias[col+n];

  #pragma unroll
  for(int m=0;m<TM;m++){
    const long row = m0 + ty*TM + m;
    const long base = row*(long)N + col;
    float o[TN];
    #pragma unroll
    for(int j=0;j<TN/2;j++){ float2 f=upk(acc[m][j]); o[2*j]=f.x+bv[2*j]; o[2*j+1]=f.y+bv[2*j+1]; }
    if constexpr (MODE==1){
      #pragma unroll
      for(int n=0;n<TN;n++) o[n]=fmaxf(o[n],0.f);
    } else if constexpr (MODE==2){
      #pragma unroll
      for(int n=0;n<TN;n++) o[n]=fmaxf(o[n],0.f)*mul[base+n];
    } else if constexpr (MODE==3){
      #pragma unroll
      for(int n=0;n<TN;n++) o[n]=fmaxf(o[n]*mul[base+n],0.f);
    }
    #pragma unroll
    for(int j=0;j<TN/4;j++)
      *(float4*)&C[base + 4*j] = make_float4(o[4*j],o[4*j+1],o[4*j+2],o[4*j+3]);
  }
}

// ---------------- softmax over last dim ----------------
__global__ void softmax_k(const float* __restrict__ p, float* __restrict__ out, int nrows){
  int idx = blockIdx.x*256 + threadIdx.x;
  if(idx >= nrows) return;
  float4 v0 = *(const float4*)(p + (long)idx*8);
  float4 v1 = *(const float4*)(p + (long)idx*8 + 4);
  float v[8]={v0.x,v0.y,v0.z,v0.w,v1.x,v1.y,v1.z,v1.w};
  float m=v[0];
  #pragma unroll
  for(int j=1;j<8;j++) m=fmaxf(m,v[j]);
  float s=0.f;
  #pragma unroll
  for(int j=0;j<8;j++){ v[j]=expf(v[j]-m); s+=v[j]; }
  float inv=1.f/s;
  #pragma unroll
  for(int j=0;j<8;j++) v[j]*=inv;
  *(float4*)(out + (long)idx*8)   = make_float4(v[0],v[1],v[2],v[3]);
  *(float4*)(out + (long)idx*8+4) = make_float4(v[4],v[5],v[6],v[7]);
}

// ---------------- mix layer0 -> fp16 (1-term) ----------------
__global__ void mix_k(const float* __restrict__ he, const float* __restrict__ probs,
                      __half* __restrict__ xh){
  const int b = blockIdx.x;
  __shared__ float p[64];
  if(threadIdx.x<64) p[threadIdx.x]=probs[b*64+threadIdx.x];
  __syncthreads();
  const int d = threadIdx.x*4;
  float4 h[8];
  #pragma unroll
  for(int j=0;j<8;j++) h[j]=*(const float4*)(he + ((long)j*8192+b)*1024 + d);
  #pragma unroll
  for(int i=0;i<8;i++){
    float4 a=make_float4(0.f,0.f,0.f,0.f);
    #pragma unroll
    for(int j=0;j<8;j++){
      float w=p[i*8+j];
      a.x+=w*h[j].x; a.y+=w*h[j].y; a.z+=w*h[j].z; a.w+=w*h[j].w;
    }
    const long base = ((long)i*8192+b)*1024 + d;
    *(__half2*)(xh+base)   = __halves2half2(__float2half_rn(a.x),__float2half_rn(a.y));
    *(__half2*)(xh+base+2) = __halves2half2(__float2half_rn(a.z),__float2half_rn(a.w));
  }
}

// ---------------- fused mix(layer1) + heads ----------------
__global__ void heads_mix_k(const float* __restrict__ he, const float* __restrict__ probs,
                            const float* __restrict__ aW, const float* __restrict__ ab,
                            const float* __restrict__ cW, const float* __restrict__ cb,
                            float* __restrict__ out){
  const int b=blockIdx.x, tid=threadIdx.x, lane=tid&31, wid=tid>>5;
  __shared__ float p[64];
  if(tid<64) p[tid]=probs[b*64+tid];
  __syncthreads();
  const int d = tid*4;
  float4 h[8];
  #pragma unroll
  for(int j=0;j<8;j++) h[j]=*(const float4*)(he + ((long)j*8192+b)*1024 + d);

  float acc[9];
  #pragma unroll
  for(int o=0;o<9;o++) acc[o]=0.f;
  #pragma unroll
  for(int e=0;e<8;e++){
    float4 xv=make_float4(0.f,0.f,0.f,0.f);
    #pragma unroll
    for(int j=0;j<8;j++){
      float w=p[e*8+j];
      xv.x+=w*h[j].x; xv.y+=w*h[j].y; xv.z+=w*h[j].z; xv.w+=w*h[j].w;
    }
    const float* aw = aW + ((long)e*1024 + d)*8;
    const float* cw = cW + (long)e*1024 + d;
    float vv[4]={xv.x,xv.y,xv.z,xv.w};
    #pragma unroll
    for(int c=0;c<4;c++){
      float4 w0=*(const float4*)(aw + c*8);
      float4 w1=*(const float4*)(aw + c*8+4);
      float v=vv[c];
      acc[0]+=v*w0.x; acc[1]+=v*w0.y; acc[2]+=v*w0.z; acc[3]+=v*w0.w;
      acc[4]+=v*w1.x; acc[5]+=v*w1.y; acc[6]+=v*w1.z; acc[7]+=v*w1.w;
      acc[8]+=v*cw[c];
    }
  }
  #pragma unroll
  for(int o=0;o<9;o++){
    #pragma unroll
    for(int s=16;s>0;s>>=1) acc[o] += __shfl_down_sync(0xffffffffu, acc[o], s);
  }
  __shared__ float red[8][9];
  if(lane==0){
    #pragma unroll
    for(int o=0;o<9;o++) red[wid][o]=acc[o];
  }
  __syncthreads();
  if(tid<9){
    float s=0.f;
    #pragma unroll
    for(int w=0;w<8;w++) s+=red[w][tid];
    float bs=0.f;
    if(tid<8){ for(int e=0;e<8;e++) bs+=ab[e*8+tid]; out[(long)b*8+tid]=s+bs; }
    else     { for(int e=0;e<8;e++) bs+=cb[e];       out[65536+b]=s+bs; }
  }
}

// ---------------- launch ----------------
extern "C" void kernel_launch(void* const* d_in, const int* in_sizes, int n_in,
                              void* d_out, int out_size)
{
  const float* x    = (const float*)d_in[0];
  const float* sW1  = (const float*)d_in[1];
  const float* sb1  = (const float*)d_in[2];
  const float* sW2  = (const float*)d_in[3];
  const float* sb2  = (const float*)d_in[4];
  const float* sW3  = (const float*)d_in[5];
  const float* sb3  = (const float*)d_in[6];
  const float* tW   = (const float*)d_in[7];
  const float* tb   = (const float*)d_in[8];
  const float* rdW  = (const float*)d_in[9];
  const float* rdb  = (const float*)d_in[10];
  const float* ruW  = (const float*)d_in[11];
  const float* rub  = (const float*)d_in[12];
  const float* eW   = (const float*)d_in[13];
  const float* eb   = (const float*)d_in[14];
  const float* aW   = (const float*)d_in[15];
  const float* ab   = (const float*)d_in[16];
  const float* cW   = (const float*)d_in[17];
  const float* cb   = (const float*)d_in[18];
  float* out = (float*)d_out;

  float *f,*r,*q,*p,*pr,*he;
  cudaGetSymbolAddress((void**)&f , g_f );
  cudaGetSymbolAddress((void**)&r , g_r );
  cudaGetSymbolAddress((void**)&q , g_q );
  cudaGetSymbolAddress((void**)&p , g_p );
  cudaGetSymbolAddress((void**)&pr, g_pr);
  cudaGetSymbolAddress((void**)&he, g_he);

  __half *xoh,*xol,*h1h,*h1l,*h2h,*h2l,*fh,*xxh;
  __half *w1h,*w2h,*w3h,*weh;
  cudaGetSymbolAddress((void**)&xoh, g_xoh); cudaGetSymbolAddress((void**)&xol, g_xol);
  cudaGetSymbolAddress((void**)&h1h, g_h1h); cudaGetSymbolAddress((void**)&h1l, g_h1l);
  cudaGetSymbolAddress((void**)&h2h, g_h2h); cudaGetSymbolAddress((void**)&h2l, g_h2l);
  cudaGetSymbolAddress((void**)&fh , g_fh );
  cudaGetSymbolAddress((void**)&xxh, g_xxh);
  cudaGetSymbolAddress((void**)&w1h, g_w1h);
  cudaGetSymbolAddress((void**)&w2h, g_w2h);
  cudaGetSymbolAddress((void**)&w3h, g_w3h);
  cudaGetSymbolAddress((void**)&weh, g_weh);

  constexpr int SMEM_T2 = 4*49152 + 1024;   // ATERMS=2: 4 stages
  constexpr int SMEM_T1 = 6*32768 + 1024;   // ATERMS=1: 6 stages
  cudaFuncSetAttribute(tc_gemm<1,false,2,2>, cudaFuncAttributeMaxDynamicSharedMemorySize, SMEM_T2);
  cudaFuncSetAttribute(tc_gemm<0,true ,1,2>, cudaFuncAttributeMaxDynamicSharedMemorySize, SMEM_T2);
  cudaFuncSetAttribute(tc_gemm<1,true ,0,1>, cudaFuncAttributeMaxDynamicSharedMemorySize, SMEM_T1);

  cudaStream_t s2;
  cudaStreamCreateWithFlags(&s2, cudaStreamNonBlocking);
  cudaEvent_t eFork, eWts, eTrunk, eRoute;
  cudaEventCreateWithFlags(&eFork,  cudaEventDisableTiming);
  cudaEventCreateWithFlags(&eWts,   cudaEventDisableTiming);
  cudaEventCreateWithFlags(&eTrunk, cudaEventDisableTiming);
  cudaEventCreateWithFlags(&eRoute, cudaEventDisableTiming);

  dim3 blk(256);

  // ---- fork: expert-weight prep on s2, overlapped with trunk ----
  cudaEventRecord(eFork, 0);
  cudaStreamWaitEvent(s2, eFork, 0);
  tsp_k<<<dim3(32,32,16),blk,0,s2>>>(eW, weh, 1024, 1024);
  cudaEventRecord(eWts, s2);

  // ---- main: trunk weight prep + trunk GEMMs (fp16 2-term A) ----
  tsp_k<<<dim3(16, 4, 1),blk>>>(sW1, w1h, 128, 512);
  tsp_k<<<dim3(16,16, 1),blk>>>(sW2, w2h, 512, 512);
  tsp_k<<<dim3(32,16, 1),blk>>>(sW3, w3h, 512, 1024);
  cvt_split_k<<<1024,blk>>>(x, 192, 128, xoh, xol, 8192L*128);
  tc_gemm<1,false,2,2><<<dim3(4,64,1),blk,SMEM_T2>>>(
      xoh,xol,0,128, w1h,0, sb1,0, nullptr, h1h,h1l,0, 512,128);
  tc_gemm<1,false,2,2><<<dim3(4,64,1),blk,SMEM_T2>>>(
      h1h,h1l,0,512, w2h,0, sb2,0, nullptr, h2h,h2l,0, 512,512);
  tc_gemm<0,true,1,2><<<dim3(8,64,1),blk,SMEM_T2>>>(
      h2h,h2l,0,512, w3h,0, sb3,0, f, fh,nullptr,0, 1024,512);
  cudaEventRecord(eTrunk, 0);

  // ---- s2: routing chain (fma pipe), overlapped with expert L0 GEMM ----
  cudaStreamWaitEvent(s2, eTrunk, 0);
  gemm_k<128,128,2,false><<<dim3(8,64,1),blk,0,s2>>>(x+128,192,0, tW,0, tb,0, f, r,0, 8192,1024,64);
  gemm_k<64,64,0,true ><<<dim3(1,128,1),blk,0,s2>>>(r,1024,0, rdW,0, rdb,0, nullptr, p,0, 8192,64,1024);
  gemm_k<128,128,3,false><<<dim3(8,64,1),blk,0,s2>>>(p,64,0,
      ruW,0, rub,0, r, q,0, 8192,1024,64);
  gemm_k<64,64,0,false><<<dim3(1,128,1),blk,0,s2>>>(q,1024,0,
      rdW+1024L*64,0, rdb+64,0, nullptr, p+8192L*64,0, 8192,64,1024);
  softmax_k<<<(2*8192*8+255)/256,blk,0,s2>>>(p, pr, 2*8192*8);
  cudaEventRecord(eRoute, s2);

  // ---- main: expert layer 0 (fp16 1-term A, deep prefetch) ----
  cudaStreamWaitEvent(0, eWts, 0);
  tc_gemm<1,true,0,1><<<dim3(8,64,8),blk,SMEM_T1>>>(
      fh,nullptr,0,1024, weh,1048576, eb,1024, he, nullptr,nullptr,8388608, 1024,1024);

  // ---- join: mixing needs routing probs ----
  cudaStreamWaitEvent(0, eRoute, 0);
  mix_k<<<8192,blk>>>(he, pr, xxh);

  // expert layer 1 (fp16 1-term A, deep prefetch)
  tc_gemm<1,true,0,1><<<dim3(8,64,8),blk,SMEM_T1>>>(
      xxh,nullptr,8388608,1024, weh+8L*1048576,1048576, eb+8192,1024,
      he, nullptr,nullptr,8388608, 1024,1024);

  // fused mix(layer1) + heads
  heads_mix_k<<<8192,blk>>>(he, pr+8192*64, aW, ab, cW, cb, out);
}

// round 15
// speedup vs baseline: 1.6443x; 1.0685x over previous
#include <cuda_runtime.h>
#include <cuda_fp16.h>
#include <cstdint>

typedef unsigned long long u64;
typedef uint32_t u32;

// ---------------- scratch (device globals, no allocations) ----------------
__device__ float g_f [8192*1024];
__device__ float g_r [8192*1024];
__device__ float g_q [8192*1024];
__device__ float g_p [3*8192*64];
__device__ float g_pr[3*8192*64];
__device__ float g_he[8ull*8192*1024];

__device__ __half g_xoh[8192*128],  g_xol[8192*128];
__device__ __half g_h1h[8192*512],  g_h1l[8192*512];
__device__ __half g_h2h[8192*512],  g_h2l[8192*512];
__device__ __half g_fh [8192*1024];
__device__ __half g_xxh[8ull*8192*1024];
__device__ __half g_w1h[512*128];
__device__ __half g_w2h[512*512];
__device__ __half g_w3h[1024*512];
__device__ __half g_weh[16ull*1024*1024];

// ---------------- PTX helpers (family-portable: sm_80+) ----------------
__device__ __forceinline__ u32 smem_u32(const void* p){
  u32 a; asm("{ .reg .u64 t; cvta.to.shared.u64 t, %1; cvt.u32.u64 %0, t; }" : "=r"(a) : "l"(p)); return a;
}
#define CP16(d,s) asm volatile("cp.async.cg.shared.global [%0], [%1], 16;" :: "r"(d), "l"(s) : "memory")
#define CP_COMMIT() asm volatile("cp.async.commit_group;" ::: "memory")
#define CP_WAIT(n)  asm volatile("cp.async.wait_group %0;" :: "n"(n) : "memory")
#define LDSM_X4(r0,r1,r2,r3,a) \
  asm volatile("ldmatrix.sync.aligned.m8n8.x4.shared.b16 {%0,%1,%2,%3}, [%4];" \
    : "=r"(r0),"=r"(r1),"=r"(r2),"=r"(r3) : "r"(a))
#define MMA16816H(c,a0,a1,a2,a3,b0,b1) \
  asm volatile("mma.sync.aligned.m16n8k16.row.col.f32.f16.f16.f32 " \
    "{%0,%1,%2,%3},{%4,%5,%6,%7},{%8,%9},{%0,%1,%2,%3};" \
    : "+f"((c)[0]),"+f"((c)[1]),"+f"((c)[2]),"+f"((c)[3]) \
    : "r"(a0),"r"(a1),"r"(a2),"r"(a3),"r"(b0),"r"(b1))
#define SWZ(o) ((o) ^ (((o) >> 3) & 0x70))

// ---------------- fp16 split (input x only) ----------------
__global__ void cvt_split_k(const float* __restrict__ in, int lda, int cols,
                            __half* __restrict__ hi, __half* __restrict__ lo, long total){
  long idx = ((long)blockIdx.x*256 + threadIdx.x)*4;
  if(idx >= total) return;
  long row = idx / cols; int col = (int)(idx % cols);
  float4 v = *(const float4*)(in + row*lda + col);
  float vv[4] = {v.x, v.y, v.z, v.w};
  __half h[4], l[4];
  #pragma unroll
  for(int j=0;j<4;j++){
    h[j] = __float2half_rn(vv[j]);
    l[j] = __float2half_rn(vv[j] - __half2float(h[j]));
  }
  *(__half2*)(hi+idx)   = __halves2half2(h[0],h[1]);
  *(__half2*)(hi+idx+2) = __halves2half2(h[2],h[3]);
  *(__half2*)(lo+idx)   = __halves2half2(l[0],l[1]);
  *(__half2*)(lo+idx+2) = __halves2half2(l[2],l[3]);
}

// transpose: W[z][Kd][Nd] fp32 -> [z][Nd][Kd] fp16
__global__ void tsp_k(const float* __restrict__ W, __half* __restrict__ Wh, int Kd, int Nd){
  __shared__ float t[32][33];
  long z = blockIdx.z;
  const float* Wz = W + z*(long)Kd*Nd;
  __half* Hz = Wh + z*(long)Kd*Nd;
  int kb = blockIdx.y*32, nb = blockIdx.x*32;
  int tx = threadIdx.x & 31, ty = threadIdx.x >> 5;
  #pragma unroll
  for(int r=0;r<32;r+=8) t[ty+r][tx] = Wz[(long)(kb+ty+r)*Nd + nb+tx];
  __syncthreads();
  #pragma unroll
  for(int r=0;r<32;r+=8)
    Hz[(long)(nb+ty+r)*Kd + kb+tx] = __float2half_rn(t[tx][ty+r]);
}

// ---------------- trunk HMMA GEMM, tile 128x128, BK=64, fp16 2-term --------
__device__ __forceinline__ void stage_load2(u32 sbase,
    const __half* __restrict__ Ah, const __half* __restrict__ Al, int m0, int lda,
    const __half* __restrict__ Wh, int n0, int ldw,
    int k0, int tid){
  #pragma unroll
  for(int t=0;t<4;t++){
    int idx = tid + t*256;
    int row = idx >> 3, c8 = idx & 7;
    u32 sw = SWZ((u32)(row*128 + c8*16));
    long ao = (long)(m0+row)*lda + k0 + c8*8;
    long wo = (long)(n0+row)*ldw + k0 + c8*8;
    CP16(sbase + sw,         Ah + ao);
    CP16(sbase + 16384 + sw, Al + ao);
    CP16(sbase + 32768 + sw, Wh + wo);
  }
}

// MODE 0: none, 1: relu. WF32: write fp32 C. WSPLIT 0: none, 1: fp16 hi, 2: hi+lo.
template<int MODE, bool WF32, int WSPLIT>
__global__ void __launch_bounds__(256,1) tc_gemm(
    const __half* __restrict__ Ahi, const __half* __restrict__ Alo, long sA, int lda,
    const __half* __restrict__ Whi, long sW,
    const float* __restrict__ bias, long sB,
    float* __restrict__ C,
    __half* __restrict__ Chi, __half* __restrict__ Clo, long sC,
    int N, int K)
{
  constexpr int STG = 49152;
  extern __shared__ char smem[];
  const int tid = threadIdx.x, wid = tid >> 5, lane = tid & 31;
  const long z = blockIdx.z;
  Ahi += z*sA; Alo += z*sA;
  Whi += z*sW; bias += z*sB;
  if(WF32)       C   += z*sC;
  if(WSPLIT>=1)  Chi += z*sC;
  if(WSPLIT==2)  Clo += z*sC;
  const int m0 = blockIdx.y*128, n0 = blockIdx.x*128;
  const int mrow0 = (wid >> 1)*32, ncol0 = (wid & 1)*64;
  u32 sb = smem_u32(smem);
  float* bias_s = (float*)(smem + 4*STG);
  if(tid < 128) bias_s[tid] = bias[n0+tid];

  const int arow = mrow0 + (lane & 15);
  const u32 akh  = ((lane >> 4) & 1) * 16;
  const int bn   = ncol0 + (lane & 7) + ((lane >> 4) & 1) * 8;
  const u32 bkh  = ((lane >> 3) & 1) * 16;

  float acc[2][8][4];
  #pragma unroll
  for(int a=0;a<2;a++)
    #pragma unroll
    for(int b=0;b<8;b++)
      #pragma unroll
      for(int c=0;c<4;c++) acc[a][b][c]=0.f;

  const int nchunks = K >> 6;
  stage_load2(sb, Ahi, Alo, m0, lda, Whi, n0, K, 0, tid);
  CP_COMMIT();
  if(nchunks > 1){
    stage_load2(sb + STG, Ahi, Alo, m0, lda, Whi, n0, K, 64, tid);
    CP_COMMIT();
  }

  for(int i=0;i<nchunks;i++){
    if(i+2 < nchunks){
      int buf = (i+2)&3;
      stage_load2(sb + buf*STG, Ahi, Alo, m0, lda, Whi, n0, K, (i+2)*64, tid);
      CP_COMMIT();
      CP_WAIT(2);
    } else if(i+1 < nchunks){
      CP_WAIT(1);
    } else {
      CP_WAIT(0);
    }
    __syncthreads();
    u32 sbase = sb + (i&3)*STG;
    #pragma unroll
    for(int k=0;k<4;k++){
      u32 ah[2][4], al[2][4], bh[4][4];
      #pragma unroll
      for(int mt=0;mt<2;mt++){
        u32 sw = SWZ((u32)((arow + mt*16)*128) + k*32 + akh);
        LDSM_X4(ah[mt][0],ah[mt][1],ah[mt][2],ah[mt][3], sbase + sw);
        LDSM_X4(al[mt][0],al[mt][1],al[mt][2],al[mt][3], sbase + 16384 + sw);
      }
      #pragma unroll
      for(int ng=0;ng<4;ng++){
        u32 sw = SWZ((u32)((bn + ng*16)*128) + k*32 + bkh);
        LDSM_X4(bh[ng][0],bh[ng][1],bh[ng][2],bh[ng][3], sbase + 32768u + sw);
      }
      #pragma unroll
      for(int ng=0;ng<4;ng++)
        #pragma unroll
        for(int mt=0;mt<2;mt++){
          MMA16816H(acc[mt][ng*2+0], ah[mt][0],ah[mt][1],ah[mt][2],ah[mt][3], bh[ng][0],bh[ng][1]);
          MMA16816H(acc[mt][ng*2+1], ah[mt][0],ah[mt][1],ah[mt][2],ah[mt][3], bh[ng][2],bh[ng][3]);
        }
      #pragma unroll
      for(int ng=0;ng<4;ng++)
        #pragma unroll
        for(int mt=0;mt<2;mt++){
          MMA16816H(acc[mt][ng*2+0], al[mt][0],al[mt][1],al[mt][2],al[mt][3], bh[ng][0],bh[ng][1]);
          MMA16816H(acc[mt][ng*2+1], al[mt][0],al[mt][1],al[mt][2],al[mt][3], bh[ng][2],bh[ng][3]);
        }
    }
  }

  #pragma unroll
  for(int mt=0;mt<2;mt++){
    const long r0 = m0 + mrow0 + mt*16 + (lane >> 2);
    #pragma unroll
    for(int nt=0;nt<8;nt++){
      const int lc = ncol0 + nt*8 + (lane & 3)*2;
      const float b0 = bias_s[lc], b1 = bias_s[lc+1];
      float v0 = acc[mt][nt][0]+b0, v1 = acc[mt][nt][1]+b1;
      float v2 = acc[mt][nt][2]+b0, v3 = acc[mt][nt][3]+b1;
      if(MODE == 1){
        v0=fmaxf(v0,0.f); v1=fmaxf(v1,0.f); v2=fmaxf(v2,0.f); v3=fmaxf(v3,0.f);
      }
      const long o0 = r0*(long)N + n0 + lc, o1 = (r0+8)*(long)N + n0 + lc;
      if(WF32){
        *(float2*)&C[o0] = make_float2(v0,v1);
        *(float2*)&C[o1] = make_float2(v2,v3);
      }
      if(WSPLIT >= 1){
        __half h0=__float2half_rn(v0), h1=__float2half_rn(v1);
        __half h2=__float2half_rn(v2), h3=__float2half_rn(v3);
        *(__half2*)&Chi[o0] = __halves2half2(h0,h1);
        *(__half2*)&Chi[o1] = __halves2half2(h2,h3);
        if(WSPLIT == 2){
          *(__half2*)&Clo[o0] = __halves2half2(
              __float2half_rn(v0-__half2float(h0)), __float2half_rn(v1-__half2float(h1)));
          *(__half2*)&Clo[o1] = __halves2half2(
              __float2half_rn(v2-__half2float(h2)), __float2half_rn(v3-__half2float(h3)));
        }
      }
    }
  }
}

// ---------------- expert HMMA GEMM: tile 256x128, warp 64x64, fp16 1-term --
// Fat warp tiles cut LDSM smem traffic (MMA:LDSM = 4:1); 4 stages x 48KB,
// prefetch distance 2 (chunks are 2x heavier than the 128-row kernel).
__device__ __forceinline__ void stage_load_big(u32 sbase,
    const __half* __restrict__ Ah, int m0, int lda,
    const __half* __restrict__ Wh, int n0, int ldw,
    int k0, int tid){
  #pragma unroll
  for(int t=0;t<8;t++){            // A: 256 rows x 8 f4
    int idx = tid + t*256;
    int row = idx >> 3, c8 = idx & 7;
    u32 sw = SWZ((u32)(row*128 + c8*16));
    CP16(sbase + sw, Ah + (long)(m0+row)*lda + k0 + c8*8);
  }
  #pragma unroll
  for(int t=0;t<4;t++){            // W: 128 rows x 8 f4
    int idx = tid + t*256;
    int row = idx >> 3, c8 = idx & 7;
    u32 sw = SWZ((u32)(row*128 + c8*16));
    CP16(sbase + 32768u + sw, Wh + (long)(n0+row)*ldw + k0 + c8*8);
  }
}

__global__ void __launch_bounds__(256,1) tc_gemm_big(
    const __half* __restrict__ Ah, long sA, int lda,
    const __half* __restrict__ Wh, long sW,
    const float* __restrict__ bias, long sB,
    float* __restrict__ C, long sC,
    int N, int K)
{
  constexpr int STG = 49152;
  extern __shared__ char smem[];
  const int tid = threadIdx.x, wid = tid >> 5, lane = tid & 31;
  const long z = blockIdx.z;
  Ah += z*sA; Wh += z*sW; bias += z*sB; C += z*sC;
  const int m0 = blockIdx.y*256, n0 = blockIdx.x*128;
  const int mrow0 = (wid >> 1)*64, ncol0 = (wid & 1)*64;
  u32 sb = smem_u32(smem);
  float* bias_s = (float*)(smem + 4*STG);
  if(tid < 128) bias_s[tid] = bias[n0+tid];

  const int arow = mrow0 + (lane & 15);
  const u32 akh  = ((lane >> 4) & 1) * 16;
  const int bn   = ncol0 + (lane & 7) + ((lane >> 4) & 1) * 8;
  const u32 bkh  = ((lane >> 3) & 1) * 16;

  float acc[4][8][4];
  #pragma unroll
  for(int a=0;a<4;a++)
    #pragma unroll
    for(int b=0;b<8;b++)
      #pragma unroll
      for(int c=0;c<4;c++) acc[a][b][c]=0.f;

  const int nchunks = K >> 6;
  stage_load_big(sb, Ah, m0, lda, Wh, n0, K, 0, tid);
  CP_COMMIT();
  if(nchunks > 1){
    stage_load_big(sb + STG, Ah, m0, lda, Wh, n0, K, 64, tid);
    CP_COMMIT();
  }

  for(int i=0;i<nchunks;i++){
    if(i+2 < nchunks){
      int buf = (i+2)&3;
      stage_load_big(sb + buf*STG, Ah, m0, lda, Wh, n0, K, (i+2)*64, tid);
      CP_COMMIT();
      CP_WAIT(2);
    } else if(i+1 < nchunks){
      CP_WAIT(1);
    } else {
      CP_WAIT(0);
    }
    __syncthreads();
    u32 sbase = sb + (i&3)*STG;
    #pragma unroll
    for(int k=0;k<4;k++){
      u32 ah[4][4], bh[4][4];
      #pragma unroll
      for(int mt=0;mt<4;mt++){
        u32 sw = SWZ((u32)((arow + mt*16)*128) + k*32 + akh);
        LDSM_X4(ah[mt][0],ah[mt][1],ah[mt][2],ah[mt][3], sbase + sw);
      }
      #pragma unroll
      for(int ng=0;ng<4;ng++){
        u32 sw = SWZ((u32)((bn + ng*16)*128) + k*32 + bkh);
        LDSM_X4(bh[ng][0],bh[ng][1],bh[ng][2],bh[ng][3], sbase + 32768u + sw);
      }
      #pragma unroll
      for(int ng=0;ng<4;ng++)
        #pragma unroll
        for(int mt=0;mt<4;mt++){
          MMA16816H(acc[mt][ng*2+0], ah[mt][0],ah[mt][1],ah[mt][2],ah[mt][3], bh[ng][0],bh[ng][1]);
          MMA16816H(acc[mt][ng*2+1], ah[mt][0],ah[mt][1],ah[mt][2],ah[mt][3], bh[ng][2],bh[ng][3]);
        }
    }
    // no trailing barrier: 4-stage ring, distance 2 -> no WAR hazard
  }

  #pragma unroll
  for(int mt=0;mt<4;mt++){
    const long r0 = m0 + mrow0 + mt*16 + (lane >> 2);
    #pragma unroll
    for(int nt=0;nt<8;nt++){
      const int lc = ncol0 + nt*8 + (lane & 3)*2;
      const float b0 = bias_s[lc], b1 = bias_s[lc+1];
      float v0 = fmaxf(acc[mt][nt][0]+b0, 0.f);
      float v1 = fmaxf(acc[mt][nt][1]+b1, 0.f);
      float v2 = fmaxf(acc[mt][nt][2]+b0, 0.f);
      float v3 = fmaxf(acc[mt][nt][3]+b1, 0.f);
      *(float2*)&C[ r0   *(long)N + n0 + lc] = make_float2(v0,v1);
      *(float2*)&C[(r0+8)*(long)N + n0 + lc] = make_float2(v2,v3);
    }
  }
}

// ---------------- f32x2 SGEMM (gate + routing) ----------------
__device__ __forceinline__ u64 pk2(float lo, float hi){
  u64 r; asm("mov.b64 %0, {%1, %2};" : "=l"(r) : "f"(lo), "f"(hi)); return r;
}
__device__ __forceinline__ void fma2(u64 &d, u64 a, u64 b){
  asm("fma.rn.f32x2 %0, %1, %2, %0;" : "+l"(d) : "l"(a), "l"(b));
}
__device__ __forceinline__ float2 upk(u64 v){
  float2 f; asm("mov.b64 {%0, %1}, %2;" : "=f"(f.x), "=f"(f.y) : "l"(v)); return f;
}

template<int BM, int BN, int MODE, bool RELUA>
__global__ void __launch_bounds__(256, (BM==64?3:2)) gemm_k(
    const float* __restrict__ A, int lda, long sA,
    const float* __restrict__ W, long sW,
    const float* __restrict__ bias, long sB,
    const float* __restrict__ mul,
    float* __restrict__ C, long sC,
    int M, int N, int K)
{
  constexpr int BK=16, TN=BN/16, TM=BM/16;
  __shared__ float As[BK][BM];
  __shared__ float Ws[BK][BN];
  const int z = blockIdx.z;
  A += (long)z*sA; W += (long)z*sW; bias += (long)z*sB; C += (long)z*sC;
  const int m0 = blockIdx.y*BM;
  const int n0 = blockIdx.x*BN;
  const int tid = threadIdx.x;
  const int tx = tid & 15, ty = tid >> 4;

  u64 acc[TM][TN/2];
  #pragma unroll
  for(int i=0;i<TM;i++)
    #pragma unroll
    for(int j=0;j<TN/2;j++) acc[i][j]=0ull;

  for(int k0=0;k0<K;k0+=BK){
    #pragma unroll
    for(int idx4=tid; idx4 < BM*4; idx4+=256){
      int row = idx4 >> 2;
      int c4  = (idx4 & 3)*4;
      float4 v = *(const float4*)(A + (long)(m0+row)*lda + k0 + c4);
      if(RELUA){ v.x=fmaxf(v.x,0.f); v.y=fmaxf(v.y,0.f); v.z=fmaxf(v.z,0.f); v.w=fmaxf(v.w,0.f); }
      As[c4+0][row]=v.x; As[c4+1][row]=v.y; As[c4+2][row]=v.z; As[c4+3][row]=v.w;
    }
    #pragma unroll
    for(int idx=tid; idx < BK*BN/4; idx+=256){
      int row = idx / (BN/4);
      int c4  = (idx % (BN/4))*4;
      *(float4*)&Ws[row][c4] = *(const float4*)(W + (long)(k0+row)*N + n0 + c4);
    }
    __syncthreads();
    #pragma unroll
    for(int kk=0;kk<BK;kk++){
      u64 ap[TM];
      #pragma unroll
      for(int j=0;j<TM/4;j++){
        float4 a0 = *(const float4*)&As[kk][ty*TM + j*4];
        ap[j*4+0]=pk2(a0.x,a0.x); ap[j*4+1]=pk2(a0.y,a0.y);
        ap[j*4+2]=pk2(a0.z,a0.z); ap[j*4+3]=pk2(a0.w,a0.w);
      }
      u64 wp[TN/2];
      #pragma unroll
      for(int j=0;j<TN/4;j++){
        float4 w0 = *(const float4*)&Ws[kk][tx*TN + j*4];
        wp[j*2+0]=pk2(w0.x,w0.y); wp[j*2+1]=pk2(w0.z,w0.w);
      }
      #pragma unroll
      for(int m=0;m<TM;m++)
        #pragma unroll
        for(int j=0;j<TN/2;j++)
          fma2(acc[m][j], ap[m], wp[j]);
    }
    __syncthreads();
  }

  const int col = n0 + tx*TN;
  float bv[TN];
  #pragma unroll
  for(int n=0;n<TN;n++) bv[n]=bias[col+n];

  #pragma unroll
  for(int m=0;m<TM;m++){
    const long row = m0 + ty*TM + m;
    const long base = row*(long)N + col;
    float o[TN];
    #pragma unroll
    for(int j=0;j<TN/2;j++){ float2 f=upk(acc[m][j]); o[2*j]=f.x+bv[2*j]; o[2*j+1]=f.y+bv[2*j+1]; }
    if constexpr (MODE==1){
      #pragma unroll
      for(int n=0;n<TN;n++) o[n]=fmaxf(o[n],0.f);
    } else if constexpr (MODE==2){
      #pragma unroll
      for(int n=0;n<TN;n++) o[n]=fmaxf(o[n],0.f)*mul[base+n];
    } else if constexpr (MODE==3){
      #pragma unroll
      for(int n=0;n<TN;n++) o[n]=fmaxf(o[n]*mul[base+n],0.f);
    }
    #pragma unroll
    for(int j=0;j<TN/4;j++)
      *(float4*)&C[base + 4*j] = make_float4(o[4*j],o[4*j+1],o[4*j+2],o[4*j+3]);
  }
}

// ---------------- softmax over last dim ----------------
__global__ void softmax_k(const float* __restrict__ p, float* __restrict__ out, int nrows){
  int idx = blockIdx.x*256 + threadIdx.x;
  if(idx >= nrows) return;
  float4 v0 = *(const float4*)(p + (long)idx*8);
  float4 v1 = *(const float4*)(p + (long)idx*8 + 4);
  float v[8]={v0.x,v0.y,v0.z,v0.w,v1.x,v1.y,v1.z,v1.w};
  float m=v[0];
  #pragma unroll
  for(int j=1;j<8;j++) m=fmaxf(m,v[j]);
  float s=0.f;
  #pragma unroll
  for(int j=0;j<8;j++){ v[j]=expf(v[j]-m); s+=v[j]; }
  float inv=1.f/s;
  #pragma unroll
  for(int j=0;j<8;j++) v[j]*=inv;
  *(float4*)(out + (long)idx*8)   = make_float4(v[0],v[1],v[2],v[3]);
  *(float4*)(out + (long)idx*8+4) = make_float4(v[4],v[5],v[6],v[7]);
}

// ---------------- mix layer0 -> fp16 (1-term) ----------------
__global__ void mix_k(const float* __restrict__ he, const float* __restrict__ probs,
                      __half* __restrict__ xh){
  const int b = blockIdx.x;
  __shared__ float p[64];
  if(threadIdx.x<64) p[threadIdx.x]=probs[b*64+threadIdx.x];
  __syncthreads();
  const int d = threadIdx.x*4;
  float4 h[8];
  #pragma unroll
  for(int j=0;j<8;j++) h[j]=*(const float4*)(he + ((long)j*8192+b)*1024 + d);
  #pragma unroll
  for(int i=0;i<8;i++){
    float4 a=make_float4(0.f,0.f,0.f,0.f);
    #pragma unroll
    for(int j=0;j<8;j++){
      float w=p[i*8+j];
      a.x+=w*h[j].x; a.y+=w*h[j].y; a.z+=w*h[j].z; a.w+=w*h[j].w;
    }
    const long base = ((long)i*8192+b)*1024 + d;
    *(__half2*)(xh+base)   = __halves2half2(__float2half_rn(a.x),__float2half_rn(a.y));
    *(__half2*)(xh+base+2) = __halves2half2(__float2half_rn(a.z),__float2half_rn(a.w));
  }
}

// ---------------- fused mix(layer1) + heads ----------------
__global__ void heads_mix_k(const float* __restrict__ he, const float* __restrict__ probs,
                            const float* __restrict__ aW, const float* __restrict__ ab,
                            const float* __restrict__ cW, const float* __restrict__ cb,
                            float* __restrict__ out){
  const int b=blockIdx.x, tid=threadIdx.x, lane=tid&31, wid=tid>>5;
  __shared__ float p[64];
  if(tid<64) p[tid]=probs[b*64+tid];
  __syncthreads();
  const int d = tid*4;
  float4 h[8];
  #pragma unroll
  for(int j=0;j<8;j++) h[j]=*(const float4*)(he + ((long)j*8192+b)*1024 + d);

  float acc[9];
  #pragma unroll
  for(int o=0;o<9;o++) acc[o]=0.f;
  #pragma unroll
  for(int e=0;e<8;e++){
    float4 xv=make_float4(0.f,0.f,0.f,0.f);
    #pragma unroll
    for(int j=0;j<8;j++){
      float w=p[e*8+j];
      xv.x+=w*h[j].x; xv.y+=w*h[j].y; xv.z+=w*h[j].z; xv.w+=w*h[j].w;
    }
    const float* aw = aW + ((long)e*1024 + d)*8;
    const float* cw = cW + (long)e*1024 + d;
    float vv[4]={xv.x,xv.y,xv.z,xv.w};
    #pragma unroll
    for(int c=0;c<4;c++){
      float4 w0=*(const float4*)(aw + c*8);
      float4 w1=*(const float4*)(aw + c*8+4);
      float v=vv[c];
      acc[0]+=v*w0.x; acc[1]+=v*w0.y; acc[2]+=v*w0.z; acc[3]+=v*w0.w;
      acc[4]+=v*w1.x; acc[5]+=v*w1.y; acc[6]+=v*w1.z; acc[7]+=v*w1.w;
      acc[8]+=v*cw[c];
    }
  }
  #pragma unroll
  for(int o=0;o<9;o++){
    #pragma unroll
    for(int s=16;s>0;s>>=1) acc[o] += __shfl_down_sync(0xffffffffu, acc[o], s);
  }
  __shared__ float red[8][9];
  if(lane==0){
    #pragma unroll
    for(int o=0;o<9;o++) red[wid][o]=acc[o];
  }
  __syncthreads();
  if(tid<9){
    float s=0.f;
    #pragma unroll
    for(int w=0;w<8;w++) s+=red[w][tid];
    float bs=0.f;
    if(tid<8){ for(int e=0;e<8;e++) bs+=ab[e*8+tid]; out[(long)b*8+tid]=s+bs; }
    else     { for(int e=0;e<8;e++) bs+=cb[e];       out[65536+b]=s+bs; }
  }
}

// ---------------- launch ----------------
extern "C" void kernel_launch(void* const* d_in, const int* in_sizes, int n_in,
                              void* d_out, int out_size)
{
  const float* x    = (const float*)d_in[0];
  const float* sW1  = (const float*)d_in[1];
  const float* sb1  = (const float*)d_in[2];
  const float* sW2  = (const float*)d_in[3];
  const float* sb2  = (const float*)d_in[4];
  const float* sW3  = (const float*)d_in[5];
  const float* sb3  = (const float*)d_in[6];
  const float* tW   = (const float*)d_in[7];
  const float* tb   = (const float*)d_in[8];
  const float* rdW  = (const float*)d_in[9];
  const float* rdb  = (const float*)d_in[10];
  const float* ruW  = (const float*)d_in[11];
  const float* rub  = (const float*)d_in[12];
  const float* eW   = (const float*)d_in[13];
  const float* eb   = (const float*)d_in[14];
  const float* aW   = (const float*)d_in[15];
  const float* ab   = (const float*)d_in[16];
  const float* cW   = (const float*)d_in[17];
  const float* cb   = (const float*)d_in[18];
  float* out = (float*)d_out;

  float *f,*r,*q,*p,*pr,*he;
  cudaGetSymbolAddress((void**)&f , g_f );
  cudaGetSymbolAddress((void**)&r , g_r );
  cudaGetSymbolAddress((void**)&q , g_q );
  cudaGetSymbolAddress((void**)&p , g_p );
  cudaGetSymbolAddress((void**)&pr, g_pr);
  cudaGetSymbolAddress((void**)&he, g_he);

  __half *xoh,*xol,*h1h,*h1l,*h2h,*h2l,*fh,*xxh;
  __half *w1h,*w2h,*w3h,*weh;
  cudaGetSymbolAddress((void**)&xoh, g_xoh); cudaGetSymbolAddress((void**)&xol, g_xol);
  cudaGetSymbolAddress((void**)&h1h, g_h1h); cudaGetSymbolAddress((void**)&h1l, g_h1l);
  cudaGetSymbolAddress((void**)&h2h, g_h2h); cudaGetSymbolAddress((void**)&h2l, g_h2l);
  cudaGetSymbolAddress((void**)&fh , g_fh );
  cudaGetSymbolAddress((void**)&xxh, g_xxh);
  cudaGetSymbolAddress((void**)&w1h, g_w1h);
  cudaGetSymbolAddress((void**)&w2h, g_w2h);
  cudaGetSymbolAddress((void**)&w3h, g_w3h);
  cudaGetSymbolAddress((void**)&weh, g_weh);

  constexpr int SMEM_T2 = 4*49152 + 1024;
  cudaFuncSetAttribute(tc_gemm<1,false,2>, cudaFuncAttributeMaxDynamicSharedMemorySize, SMEM_T2);
  cudaFuncSetAttribute(tc_gemm<0,true ,1>, cudaFuncAttributeMaxDynamicSharedMemorySize, SMEM_T2);
  cudaFuncSetAttribute(tc_gemm_big, cudaFuncAttributeMaxDynamicSharedMemorySize, SMEM_T2);

  cudaStream_t s2;
  cudaStreamCreateWithFlags(&s2, cudaStreamNonBlocking);
  cudaEvent_t eFork, eWts, eTrunk, eRoute;
  cudaEventCreateWithFlags(&eFork,  cudaEventDisableTiming);
  cudaEventCreateWithFlags(&eWts,   cudaEventDisableTiming);
  cudaEventCreateWithFlags(&eTrunk, cudaEventDisableTiming);
  cudaEventCreateWithFlags(&eRoute, cudaEventDisableTiming);

  dim3 blk(256);

  // ---- fork: expert-weight prep on s2, overlapped with trunk ----
  cudaEventRecord(eFork, 0);
  cudaStreamWaitEvent(s2, eFork, 0);
  tsp_k<<<dim3(32,32,16),blk,0,s2>>>(eW, weh, 1024, 1024);
  cudaEventRecord(eWts, s2);

  // ---- main: trunk weight prep + trunk GEMMs (fp16 2-term A) ----
  tsp_k<<<dim3(16, 4, 1),blk>>>(sW1, w1h, 128, 512);
  tsp_k<<<dim3(16,16, 1),blk>>>(sW2, w2h, 512, 512);
  tsp_k<<<dim3(32,16, 1),blk>>>(sW3, w3h, 512, 1024);
  cvt_split_k<<<1024,blk>>>(x, 192, 128, xoh, xol, 8192L*128);
  tc_gemm<1,false,2><<<dim3(4,64,1),blk,SMEM_T2>>>(
      xoh,xol,0,128, w1h,0, sb1,0, nullptr, h1h,h1l,0, 512,128);
  tc_gemm<1,false,2><<<dim3(4,64,1),blk,SMEM_T2>>>(
      h1h,h1l,0,512, w2h,0, sb2,0, nullptr, h2h,h2l,0, 512,512);
  tc_gemm<0,true,1><<<dim3(8,64,1),blk,SMEM_T2>>>(
      h2h,h2l,0,512, w3h,0, sb3,0, f, fh,nullptr,0, 1024,512);
  cudaEventRecord(eTrunk, 0);

  // ---- s2: routing chain (fma pipe), overlapped with expert L0 GEMM ----
  cudaStreamWaitEvent(s2, eTrunk, 0);
  gemm_k<128,128,2,false><<<dim3(8,64,1),blk,0,s2>>>(x+128,192,0, tW,0, tb,0, f, r,0, 8192,1024,64);
  gemm_k<64,64,0,true ><<<dim3(1,128,1),blk,0,s2>>>(r,1024,0, rdW,0, rdb,0, nullptr, p,0, 8192,64,1024);
  gemm_k<128,128,3,false><<<dim3(8,64,1),blk,0,s2>>>(p,64,0,
      ruW,0, rub,0, r, q,0, 8192,1024,64);
  gemm_k<64,64,0,false><<<dim3(1,128,1),blk,0,s2>>>(q,1024,0,
      rdW+1024L*64,0, rdb+64,0, nullptr, p+8192L*64,0, 8192,64,1024);
  softmax_k<<<(2*8192*8+255)/256,blk,0,s2>>>(p, pr, 2*8192*8);
  cudaEventRecord(eRoute, s2);

  // ---- main: expert layer 0 (fat-tile fp16 1-term) ----
  cudaStreamWaitEvent(0, eWts, 0);
  tc_gemm_big<<<dim3(8,32,8),blk,SMEM_T2>>>(
      fh,0,1024, weh,1048576, eb,1024, he,8388608, 1024,1024);

  // ---- join: mixing needs routing probs ----
  cudaStreamWaitEvent(0, eRoute, 0);
  mix_k<<<8192,blk>>>(he, pr, xxh);

  // expert layer 1 (fat-tile fp16 1-term)
  tc_gemm_big<<<dim3(8,32,8),blk,SMEM_T2>>>(
      xxh,8388608,1024, weh+8L*1048576,1048576, eb+8192,1024, he,8388608, 1024,1024);

  // fused mix(layer1) + heads
  heads_mix_k<<<8192,blk>>>(he, pr+8192*64, aW, ab, cW, cb, out);
}

// round 16
// speedup vs baseline: 1.6664x; 1.0134x over previous
#include <cuda_runtime.h>
#include <cuda_fp16.h>
#include <cstdint>

typedef unsigned long long u64;
typedef uint32_t u32;

// ---------------- scratch (device globals, no allocations) ----------------
__device__ float g_f [8192*1024];
__device__ float g_r [8192*1024];
__device__ float g_q [8192*1024];
__device__ float g_p [3*8192*64];
__device__ float g_pr[3*8192*64];
__device__ __half g_heh[8ull*8192*1024];   // expert hidden, fp16 (128MB)

__device__ __half g_xoh[8192*128],  g_xol[8192*128];
__device__ __half g_h1h[8192*512],  g_h1l[8192*512];
__device__ __half g_h2h[8192*512],  g_h2l[8192*512];
__device__ __half g_fh [8192*1024];
__device__ __half g_xxh[8ull*8192*1024];
__device__ __half g_w1h[512*128];
__device__ __half g_w2h[512*512];
__device__ __half g_w3h[1024*512];
__device__ __half g_weh[16ull*1024*1024];

// ---------------- PTX helpers (family-portable: sm_80+) ----------------
__device__ __forceinline__ u32 smem_u32(const void* p){
  u32 a; asm("{ .reg .u64 t; cvta.to.shared.u64 t, %1; cvt.u32.u64 %0, t; }" : "=r"(a) : "l"(p)); return a;
}
#define CP16(d,s) asm volatile("cp.async.cg.shared.global [%0], [%1], 16;" :: "r"(d), "l"(s) : "memory")
#define CP_COMMIT() asm volatile("cp.async.commit_group;" ::: "memory")
#define CP_WAIT(n)  asm volatile("cp.async.wait_group %0;" :: "n"(n) : "memory")
#define LDSM_X4(r0,r1,r2,r3,a) \
  asm volatile("ldmatrix.sync.aligned.m8n8.x4.shared.b16 {%0,%1,%2,%3}, [%4];" \
    : "=r"(r0),"=r"(r1),"=r"(r2),"=r"(r3) : "r"(a))
#define MMA16816H(c,a0,a1,a2,a3,b0,b1) \
  asm volatile("mma.sync.aligned.m16n8k16.row.col.f32.f16.f16.f32 " \
    "{%0,%1,%2,%3},{%4,%5,%6,%7},{%8,%9},{%0,%1,%2,%3};" \
    : "+f"((c)[0]),"+f"((c)[1]),"+f"((c)[2]),"+f"((c)[3]) \
    : "r"(a0),"r"(a1),"r"(a2),"r"(a3),"r"(b0),"r"(b1))
#define SWZ(o) ((o) ^ (((o) >> 3) & 0x70))

// ---------------- fp16 split (input x only) ----------------
__global__ void cvt_split_k(const float* __restrict__ in, int lda, int cols,
                            __half* __restrict__ hi, __half* __restrict__ lo, long total){
  long idx = ((long)blockIdx.x*256 + threadIdx.x)*4;
  if(idx >= total) return;
  long row = idx / cols; int col = (int)(idx % cols);
  float4 v = *(const float4*)(in + row*lda + col);
  float vv[4] = {v.x, v.y, v.z, v.w};
  __half h[4], l[4];
  #pragma unroll
  for(int j=0;j<4;j++){
    h[j] = __float2half_rn(vv[j]);
    l[j] = __float2half_rn(vv[j] - __half2float(h[j]));
  }
  *(__half2*)(hi+idx)   = __halves2half2(h[0],h[1]);
  *(__half2*)(hi+idx+2) = __halves2half2(h[2],h[3]);
  *(__half2*)(lo+idx)   = __halves2half2(l[0],l[1]);
  *(__half2*)(lo+idx+2) = __halves2half2(l[2],l[3]);
}

// transpose: W[z][Kd][Nd] fp32 -> [z][Nd][Kd] fp16
__global__ void tsp_k(const float* __restrict__ W, __half* __restrict__ Wh, int Kd, int Nd){
  __shared__ float t[32][33];
  long z = blockIdx.z;
  const float* Wz = W + z*(long)Kd*Nd;
  __half* Hz = Wh + z*(long)Kd*Nd;
  int kb = blockIdx.y*32, nb = blockIdx.x*32;
  int tx = threadIdx.x & 31, ty = threadIdx.x >> 5;
  #pragma unroll
  for(int r=0;r<32;r+=8) t[ty+r][tx] = Wz[(long)(kb+ty+r)*Nd + nb+tx];
  __syncthreads();
  #pragma unroll
  for(int r=0;r<32;r+=8)
    Hz[(long)(nb+ty+r)*Kd + kb+tx] = __float2half_rn(t[tx][ty+r]);
}

// ---------------- trunk HMMA GEMM, tile 128x128, BK=64, fp16 2-term --------
__device__ __forceinline__ void stage_load2(u32 sbase,
    const __half* __restrict__ Ah, const __half* __restrict__ Al, int m0, int lda,
    const __half* __restrict__ Wh, int n0, int ldw,
    int k0, int tid){
  #pragma unroll
  for(int t=0;t<4;t++){
    int idx = tid + t*256;
    int row = idx >> 3, c8 = idx & 7;
    u32 sw = SWZ((u32)(row*128 + c8*16));
    long ao = (long)(m0+row)*lda + k0 + c8*8;
    long wo = (long)(n0+row)*ldw + k0 + c8*8;
    CP16(sbase + sw,         Ah + ao);
    CP16(sbase + 16384 + sw, Al + ao);
    CP16(sbase + 32768 + sw, Wh + wo);
  }
}

// MODE 0: none, 1: relu. WF32: write fp32 C. WSPLIT 0: none, 1: fp16 hi, 2: hi+lo.
template<int MODE, bool WF32, int WSPLIT>
__global__ void __launch_bounds__(256,1) tc_gemm(
    const __half* __restrict__ Ahi, const __half* __restrict__ Alo, long sA, int lda,
    const __half* __restrict__ Whi, long sW,
    const float* __restrict__ bias, long sB,
    float* __restrict__ C,
    __half* __restrict__ Chi, __half* __restrict__ Clo, long sC,
    int N, int K)
{
  constexpr int STG = 49152;
  extern __shared__ char smem[];
  const int tid = threadIdx.x, wid = tid >> 5, lane = tid & 31;
  const long z = blockIdx.z;
  Ahi += z*sA; Alo += z*sA;
  Whi += z*sW; bias += z*sB;
  if(WF32)       C   += z*sC;
  if(WSPLIT>=1)  Chi += z*sC;
  if(WSPLIT==2)  Clo += z*sC;
  const int m0 = blockIdx.y*128, n0 = blockIdx.x*128;
  const int mrow0 = (wid >> 1)*32, ncol0 = (wid & 1)*64;
  u32 sb = smem_u32(smem);
  float* bias_s = (float*)(smem + 4*STG);
  if(tid < 128) bias_s[tid] = bias[n0+tid];

  const int arow = mrow0 + (lane & 15);
  const u32 akh  = ((lane >> 4) & 1) * 16;
  const int bn   = ncol0 + (lane & 7) + ((lane >> 4) & 1) * 8;
  const u32 bkh  = ((lane >> 3) & 1) * 16;

  float acc[2][8][4];
  #pragma unroll
  for(int a=0;a<2;a++)
    #pragma unroll
    for(int b=0;b<8;b++)
      #pragma unroll
      for(int c=0;c<4;c++) acc[a][b][c]=0.f;

  const int nchunks = K >> 6;
  stage_load2(sb, Ahi, Alo, m0, lda, Whi, n0, K, 0, tid);
  CP_COMMIT();
  if(nchunks > 1){
    stage_load2(sb + STG, Ahi, Alo, m0, lda, Whi, n0, K, 64, tid);
    CP_COMMIT();
  }

  for(int i=0;i<nchunks;i++){
    if(i+2 < nchunks){
      int buf = (i+2)&3;
      stage_load2(sb + buf*STG, Ahi, Alo, m0, lda, Whi, n0, K, (i+2)*64, tid);
      CP_COMMIT();
      CP_WAIT(2);
    } else if(i+1 < nchunks){
      CP_WAIT(1);
    } else {
      CP_WAIT(0);
    }
    __syncthreads();
    u32 sbase = sb + (i&3)*STG;
    #pragma unroll
    for(int k=0;k<4;k++){
      u32 ah[2][4], al[2][4], bh[4][4];
      #pragma unroll
      for(int mt=0;mt<2;mt++){
        u32 sw = SWZ((u32)((arow + mt*16)*128) + k*32 + akh);
        LDSM_X4(ah[mt][0],ah[mt][1],ah[mt][2],ah[mt][3], sbase + sw);
        LDSM_X4(al[mt][0],al[mt][1],al[mt][2],al[mt][3], sbase + 16384 + sw);
      }
      #pragma unroll
      for(int ng=0;ng<4;ng++){
        u32 sw = SWZ((u32)((bn + ng*16)*128) + k*32 + bkh);
        LDSM_X4(bh[ng][0],bh[ng][1],bh[ng][2],bh[ng][3], sbase + 32768u + sw);
      }
      #pragma unroll
      for(int ng=0;ng<4;ng++)
        #pragma unroll
        for(int mt=0;mt<2;mt++){
          MMA16816H(acc[mt][ng*2+0], ah[mt][0],ah[mt][1],ah[mt][2],ah[mt][3], bh[ng][0],bh[ng][1]);
          MMA16816H(acc[mt][ng*2+1], ah[mt][0],ah[mt][1],ah[mt][2],ah[mt][3], bh[ng][2],bh[ng][3]);
        }
      #pragma unroll
      for(int ng=0;ng<4;ng++)
        #pragma unroll
        for(int mt=0;mt<2;mt++){
          MMA16816H(acc[mt][ng*2+0], al[mt][0],al[mt][1],al[mt][2],al[mt][3], bh[ng][0],bh[ng][1]);
          MMA16816H(acc[mt][ng*2+1], al[mt][0],al[mt][1],al[mt][2],al[mt][3], bh[ng][2],bh[ng][3]);
        }
    }
  }

  #pragma unroll
  for(int mt=0;mt<2;mt++){
    const long r0 = m0 + mrow0 + mt*16 + (lane >> 2);
    #pragma unroll
    for(int nt=0;nt<8;nt++){
      const int lc = ncol0 + nt*8 + (lane & 3)*2;
      const float b0 = bias_s[lc], b1 = bias_s[lc+1];
      float v0 = acc[mt][nt][0]+b0, v1 = acc[mt][nt][1]+b1;
      float v2 = acc[mt][nt][2]+b0, v3 = acc[mt][nt][3]+b1;
      if(MODE == 1){
        v0=fmaxf(v0,0.f); v1=fmaxf(v1,0.f); v2=fmaxf(v2,0.f); v3=fmaxf(v3,0.f);
      }
      const long o0 = r0*(long)N + n0 + lc, o1 = (r0+8)*(long)N + n0 + lc;
      if(WF32){
        *(float2*)&C[o0] = make_float2(v0,v1);
        *(float2*)&C[o1] = make_float2(v2,v3);
      }
      if(WSPLIT >= 1){
        __half h0=__float2half_rn(v0), h1=__float2half_rn(v1);
        __half h2=__float2half_rn(v2), h3=__float2half_rn(v3);
        *(__half2*)&Chi[o0] = __halves2half2(h0,h1);
        *(__half2*)&Chi[o1] = __halves2half2(h2,h3);
        if(WSPLIT == 2){
          *(__half2*)&Clo[o0] = __halves2half2(
              __float2half_rn(v0-__half2float(h0)), __float2half_rn(v1-__half2float(h1)));
          *(__half2*)&Clo[o1] = __halves2half2(
              __float2half_rn(v2-__half2float(h2)), __float2half_rn(v3-__half2float(h3)));
        }
      }
    }
  }
}

// ---------------- expert HMMA GEMM: tile 256x128, warp 64x64, fp16 1-term --
// Fat warp tiles cut LDSM smem traffic; fp16 output (he) halves store traffic.
__device__ __forceinline__ void stage_load_big(u32 sbase,
    const __half* __restrict__ Ah, int m0, int lda,
    const __half* __restrict__ Wh, int n0, int ldw,
    int k0, int tid){
  #pragma unroll
  for(int t=0;t<8;t++){            // A: 256 rows x 8 f4
    int idx = tid + t*256;
    int row = idx >> 3, c8 = idx & 7;
    u32 sw = SWZ((u32)(row*128 + c8*16));
    CP16(sbase + sw, Ah + (long)(m0+row)*lda + k0 + c8*8);
  }
  #pragma unroll
  for(int t=0;t<4;t++){            // W: 128 rows x 8 f4
    int idx = tid + t*256;
    int row = idx >> 3, c8 = idx & 7;
    u32 sw = SWZ((u32)(row*128 + c8*16));
    CP16(sbase + 32768u + sw, Wh + (long)(n0+row)*ldw + k0 + c8*8);
  }
}

__global__ void __launch_bounds__(256,1) tc_gemm_big(
    const __half* __restrict__ Ah, long sA, int lda,
    const __half* __restrict__ Wh, long sW,
    const float* __restrict__ bias, long sB,
    __half* __restrict__ C, long sC,
    int N, int K)
{
  constexpr int STG = 49152;
  extern __shared__ char smem[];
  const int tid = threadIdx.x, wid = tid >> 5, lane = tid & 31;
  const long z = blockIdx.z;
  Ah += z*sA; Wh += z*sW; bias += z*sB; C += z*sC;
  const int m0 = blockIdx.y*256, n0 = blockIdx.x*128;
  const int mrow0 = (wid >> 1)*64, ncol0 = (wid & 1)*64;
  u32 sb = smem_u32(smem);
  float* bias_s = (float*)(smem + 4*STG);
  if(tid < 128) bias_s[tid] = bias[n0+tid];

  const int arow = mrow0 + (lane & 15);
  const u32 akh  = ((lane >> 4) & 1) * 16;
  const int bn   = ncol0 + (lane & 7) + ((lane >> 4) & 1) * 8;
  const u32 bkh  = ((lane >> 3) & 1) * 16;

  float acc[4][8][4];
  #pragma unroll
  for(int a=0;a<4;a++)
    #pragma unroll
    for(int b=0;b<8;b++)
      #pragma unroll
      for(int c=0;c<4;c++) acc[a][b][c]=0.f;

  const int nchunks = K >> 6;
  stage_load_big(sb, Ah, m0, lda, Wh, n0, K, 0, tid);
  CP_COMMIT();
  if(nchunks > 1){
    stage_load_big(sb + STG, Ah, m0, lda, Wh, n0, K, 64, tid);
    CP_COMMIT();
  }

  for(int i=0;i<nchunks;i++){
    if(i+2 < nchunks){
      int buf = (i+2)&3;
      stage_load_big(sb + buf*STG, Ah, m0, lda, Wh, n0, K, (i+2)*64, tid);
      CP_COMMIT();
      CP_WAIT(2);
    } else if(i+1 < nchunks){
      CP_WAIT(1);
    } else {
      CP_WAIT(0);
    }
    __syncthreads();
    u32 sbase = sb + (i&3)*STG;
    #pragma unroll
    for(int k=0;k<4;k++){
      u32 ah[4][4], bh[4][4];
      #pragma unroll
      for(int mt=0;mt<4;mt++){
        u32 sw = SWZ((u32)((arow + mt*16)*128) + k*32 + akh);
        LDSM_X4(ah[mt][0],ah[mt][1],ah[mt][2],ah[mt][3], sbase + sw);
      }
      #pragma unroll
      for(int ng=0;ng<4;ng++){
        u32 sw = SWZ((u32)((bn + ng*16)*128) + k*32 + bkh);
        LDSM_X4(bh[ng][0],bh[ng][1],bh[ng][2],bh[ng][3], sbase + 32768u + sw);
      }
      #pragma unroll
      for(int ng=0;ng<4;ng++)
        #pragma unroll
        for(int mt=0;mt<4;mt++){
          MMA16816H(acc[mt][ng*2+0], ah[mt][0],ah[mt][1],ah[mt][2],ah[mt][3], bh[ng][0],bh[ng][1]);
          MMA16816H(acc[mt][ng*2+1], ah[mt][0],ah[mt][1],ah[mt][2],ah[mt][3], bh[ng][2],bh[ng][3]);
        }
    }
    // no trailing barrier: 4-stage ring, distance 2 -> no WAR hazard
  }

  #pragma unroll
  for(int mt=0;mt<4;mt++){
    const long r0 = m0 + mrow0 + mt*16 + (lane >> 2);
    #pragma unroll
    for(int nt=0;nt<8;nt++){
      const int lc = ncol0 + nt*8 + (lane & 3)*2;
      const float b0 = bias_s[lc], b1 = bias_s[lc+1];
      float v0 = fmaxf(acc[mt][nt][0]+b0, 0.f);
      float v1 = fmaxf(acc[mt][nt][1]+b1, 0.f);
      float v2 = fmaxf(acc[mt][nt][2]+b0, 0.f);
      float v3 = fmaxf(acc[mt][nt][3]+b1, 0.f);
      *(__half2*)&C[ r0   *(long)N + n0 + lc] = __halves2half2(__float2half_rn(v0), __float2half_rn(v1));
      *(__half2*)&C[(r0+8)*(long)N + n0 + lc] = __halves2half2(__float2half_rn(v2), __float2half_rn(v3));
    }
  }
}

// ---------------- f32x2 SGEMM (gate + routing) ----------------
__device__ __forceinline__ u64 pk2(float lo, float hi){
  u64 r; asm("mov.b64 %0, {%1, %2};" : "=l"(r) : "f"(lo), "f"(hi)); return r;
}
__device__ __forceinline__ void fma2(u64 &d, u64 a, u64 b){
  asm("fma.rn.f32x2 %0, %1, %2, %0;" : "+l"(d) : "l"(a), "l"(b));
}
__device__ __forceinline__ float2 upk(u64 v){
  float2 f; asm("mov.b64 {%0, %1}, %2;" : "=f"(f.x), "=f"(f.y) : "l"(v)); return f;
}

template<int BM, int BN, int MODE, bool RELUA>
__global__ void __launch_bounds__(256, (BM==64?3:2)) gemm_k(
    const float* __restrict__ A, int lda, long sA,
    const float* __restrict__ W, long sW,
    const float* __restrict__ bias, long sB,
    const float* __restrict__ mul,
    float* __restrict__ C, long sC,
    int M, int N, int K)
{
  constexpr int BK=16, TN=BN/16, TM=BM/16;
  __shared__ float As[BK][BM];
  __shared__ float Ws[BK][BN];
  const int z = blockIdx.z;
  A += (long)z*sA; W += (long)z*sW; bias += (long)z*sB; C += (long)z*sC;
  const int m0 = blockIdx.y*BM;
  const int n0 = blockIdx.x*BN;
  const int tid = threadIdx.x;
  const int tx = tid & 15, ty = tid >> 4;

  u64 acc[TM][TN/2];
  #pragma unroll
  for(int i=0;i<TM;i++)
    #pragma unroll
    for(int j=0;j<TN/2;j++) acc[i][j]=0ull;

  for(int k0=0;k0<K;k0+=BK){
    #pragma unroll
    for(int idx4=tid; idx4 < BM*4; idx4+=256){
      int row = idx4 >> 2;
      int c4  = (idx4 & 3)*4;
      float4 v = *(const float4*)(A + (long)(m0+row)*lda + k0 + c4);
      if(RELUA){ v.x=fmaxf(v.x,0.f); v.y=fmaxf(v.y,0.f); v.z=fmaxf(v.z,0.f); v.w=fmaxf(v.w,0.f); }
      As[c4+0][row]=v.x; As[c4+1][row]=v.y; As[c4+2][row]=v.z; As[c4+3][row]=v.w;
    }
    #pragma unroll
    for(int idx=tid; idx < BK*BN/4; idx+=256){
      int row = idx / (BN/4);
      int c4  = (idx % (BN/4))*4;
      *(float4*)&Ws[row][c4] = *(const float4*)(W + (long)(k0+row)*N + n0 + c4);
    }
    __syncthreads();
    #pragma unroll
    for(int kk=0;kk<BK;kk++){
      u64 ap[TM];
      #pragma unroll
      for(int j=0;j<TM/4;j++){
        float4 a0 = *(const float4*)&As[kk][ty*TM + j*4];
        ap[j*4+0]=pk2(a0.x,a0.x); ap[j*4+1]=pk2(a0.y,a0.y);
        ap[j*4+2]=pk2(a0.z,a0.z); ap[j*4+3]=pk2(a0.w,a0.w);
      }
      u64 wp[TN/2];
      #pragma unroll
      for(int j=0;j<TN/4;j++){
        float4 w0 = *(const float4*)&Ws[kk][tx*TN + j*4];
        wp[j*2+0]=pk2(w0.x,w0.y); wp[j*2+1]=pk2(w0.z,w0.w);
      }
      #pragma unroll
      for(int m=0;m<TM;m++)
        #pragma unroll
        for(int j=0;j<TN/2;j++)
          fma2(acc[m][j], ap[m], wp[j]);
    }
    __syncthreads();
  }

  const int col = n0 + tx*TN;
  float bv[TN];
  #pragma unroll
  for(int n=0;n<TN;n++) bv[n]=bias[col+n];

  #pragma unroll
  for(int m=0;m<TM;m++){
    const long row = m0 + ty*TM + m;
    const long base = row*(long)N + col;
    float o[TN];
    #pragma unroll
    for(int j=0;j<TN/2;j++){ float2 f=upk(acc[m][j]); o[2*j]=f.x+bv[2*j]; o[2*j+1]=f.y+bv[2*j+1]; }
    if constexpr (MODE==1){
      #pragma unroll
      for(int n=0;n<TN;n++) o[n]=fmaxf(o[n],0.f);
    } else if constexpr (MODE==2){
      #pragma unroll
      for(int n=0;n<TN;n++) o[n]=fmaxf(o[n],0.f)*mul[base+n];
    } else if constexpr (MODE==3){
      #pragma unroll
      for(int n=0;n<TN;n++) o[n]=fmaxf(o[n]*mul[base+n],0.f);
    }
    #pragma unroll
    for(int j=0;j<TN/4;j++)
      *(float4*)&C[base + 4*j] = make_float4(o[4*j],o[4*j+1],o[4*j+2],o[4*j+3]);
  }
}

// ---------------- softmax over last dim ----------------
__global__ void softmax_k(const float* __restrict__ p, float* __restrict__ out, int nrows){
  int idx = blockIdx.x*256 + threadIdx.x;
  if(idx >= nrows) return;
  float4 v0 = *(const float4*)(p + (long)idx*8);
  float4 v1 = *(const float4*)(p + (long)idx*8 + 4);
  float v[8]={v0.x,v0.y,v0.z,v0.w,v1.x,v1.y,v1.z,v1.w};
  float m=v[0];
  #pragma unroll
  for(int j=1;j<8;j++) m=fmaxf(m,v[j]);
  float s=0.f;
  #pragma unroll
  for(int j=0;j<8;j++){ v[j]=expf(v[j]-m); s+=v[j]; }
  float inv=1.f/s;
  #pragma unroll
  for(int j=0;j<8;j++) v[j]*=inv;
  *(float4*)(out + (long)idx*8)   = make_float4(v[0],v[1],v[2],v[3]);
  *(float4*)(out + (long)idx*8+4) = make_float4(v[4],v[5],v[6],v[7]);
}

// ---------------- mix layer0 (he fp16) -> fp16 ----------------
__global__ void mix_k(const __half* __restrict__ he, const float* __restrict__ probs,
                      __half* __restrict__ xh){
  const int b = blockIdx.x;
  __shared__ float p[64];
  if(threadIdx.x<64) p[threadIdx.x]=probs[b*64+threadIdx.x];
  __syncthreads();
  const int d = threadIdx.x*4;
  float4 h[8];
  #pragma unroll
  for(int j=0;j<8;j++){
    const __half2* hp = (const __half2*)(he + ((long)j*8192+b)*1024 + d);
    float2 a = __half22float2(hp[0]), c = __half22float2(hp[1]);
    h[j] = make_float4(a.x, a.y, c.x, c.y);
  }
  #pragma unroll
  for(int i=0;i<8;i++){
    float4 a=make_float4(0.f,0.f,0.f,0.f);
    #pragma unroll
    for(int j=0;j<8;j++){
      float w=p[i*8+j];
      a.x+=w*h[j].x; a.y+=w*h[j].y; a.z+=w*h[j].z; a.w+=w*h[j].w;
    }
    const long base = ((long)i*8192+b)*1024 + d;
    *(__half2*)(xh+base)   = __halves2half2(__float2half_rn(a.x),__float2half_rn(a.y));
    *(__half2*)(xh+base+2) = __halves2half2(__float2half_rn(a.z),__float2half_rn(a.w));
  }
}

// ---------------- fused mix(layer1) + heads (he fp16) ----------------
__global__ void heads_mix_k(const __half* __restrict__ he, const float* __restrict__ probs,
                            const float* __restrict__ aW, const float* __restrict__ ab,
                            const float* __restrict__ cW, const float* __restrict__ cb,
                            float* __restrict__ out){
  const int b=blockIdx.x, tid=threadIdx.x, lane=tid&31, wid=tid>>5;
  __shared__ float p[64];
  if(tid<64) p[tid]=probs[b*64+tid];
  __syncthreads();
  const int d = tid*4;
  float4 h[8];
  #pragma unroll
  for(int j=0;j<8;j++){
    const __half2* hp = (const __half2*)(he + ((long)j*8192+b)*1024 + d);
    float2 a = __half22float2(hp[0]), c = __half22float2(hp[1]);
    h[j] = make_float4(a.x, a.y, c.x, c.y);
  }

  float acc[9];
  #pragma unroll
  for(int o=0;o<9;o++) acc[o]=0.f;
  #pragma unroll
  for(int e=0;e<8;e++){
    float4 xv=make_float4(0.f,0.f,0.f,0.f);
    #pragma unroll
    for(int j=0;j<8;j++){
      float w=p[e*8+j];
      xv.x+=w*h[j].x; xv.y+=w*h[j].y; xv.z+=w*h[j].z; xv.w+=w*h[j].w;
    }
    const float* aw = aW + ((long)e*1024 + d)*8;
    const float* cw = cW + (long)e*1024 + d;
    float vv[4]={xv.x,xv.y,xv.z,xv.w};
    #pragma unroll
    for(int c=0;c<4;c++){
      float4 w0=*(const float4*)(aw + c*8);
      float4 w1=*(const float4*)(aw + c*8+4);
      float v=vv[c];
      acc[0]+=v*w0.x; acc[1]+=v*w0.y; acc[2]+=v*w0.z; acc[3]+=v*w0.w;
      acc[4]+=v*w1.x; acc[5]+=v*w1.y; acc[6]+=v*w1.z; acc[7]+=v*w1.w;
      acc[8]+=v*cw[c];
    }
  }
  #pragma unroll
  for(int o=0;o<9;o++){
    #pragma unroll
    for(int s=16;s>0;s>>=1) acc[o] += __shfl_down_sync(0xffffffffu, acc[o], s);
  }
  __shared__ float red[8][9];
  if(lane==0){
    #pragma unroll
    for(int o=0;o<9;o++) red[wid][o]=acc[o];
  }
  __syncthreads();
  if(tid<9){
    float s=0.f;
    #pragma unroll
    for(int w=0;w<8;w++) s+=red[w][tid];
    float bs=0.f;
    if(tid<8){ for(int e=0;e<8;e++) bs+=ab[e*8+tid]; out[(long)b*8+tid]=s+bs; }
    else     { for(int e=0;e<8;e++) bs+=cb[e];       out[65536+b]=s+bs; }
  }
}

// ---------------- launch ----------------
extern "C" void kernel_launch(void* const* d_in, const int* in_sizes, int n_in,
                              void* d_out, int out_size)
{
  const float* x    = (const float*)d_in[0];
  const float* sW1  = (const float*)d_in[1];
  const float* sb1  = (const float*)d_in[2];
  const float* sW2  = (const float*)d_in[3];
  const float* sb2  = (const float*)d_in[4];
  const float* sW3  = (const float*)d_in[5];
  const float* sb3  = (const float*)d_in[6];
  const float* tW   = (const float*)d_in[7];
  const float* tb   = (const float*)d_in[8];
  const float* rdW  = (const float*)d_in[9];
  const float* rdb  = (const float*)d_in[10];
  const float* ruW  = (const float*)d_in[11];
  const float* rub  = (const float*)d_in[12];
  const float* eW   = (const float*)d_in[13];
  const float* eb   = (const float*)d_in[14];
  const float* aW   = (const float*)d_in[15];
  const float* ab   = (const float*)d_in[16];
  const float* cW   = (const float*)d_in[17];
  const float* cb   = (const float*)d_in[18];
  float* out = (float*)d_out;

  float *f,*r,*q,*p,*pr;
  __half *heh;
  cudaGetSymbolAddress((void**)&f , g_f );
  cudaGetSymbolAddress((void**)&r , g_r );
  cudaGetSymbolAddress((void**)&q , g_q );
  cudaGetSymbolAddress((void**)&p , g_p );
  cudaGetSymbolAddress((void**)&pr, g_pr);
  cudaGetSymbolAddress((void**)&heh, g_heh);

  __half *xoh,*xol,*h1h,*h1l,*h2h,*h2l,*fh,*xxh;
  __half *w1h,*w2h,*w3h,*weh;
  cudaGetSymbolAddress((void**)&xoh, g_xoh); cudaGetSymbolAddress((void**)&xol, g_xol);
  cudaGetSymbolAddress((void**)&h1h, g_h1h); cudaGetSymbolAddress((void**)&h1l, g_h1l);
  cudaGetSymbolAddress((void**)&h2h, g_h2h); cudaGetSymbolAddress((void**)&h2l, g_h2l);
  cudaGetSymbolAddress((void**)&fh , g_fh );
  cudaGetSymbolAddress((void**)&xxh, g_xxh);
  cudaGetSymbolAddress((void**)&w1h, g_w1h);
  cudaGetSymbolAddress((void**)&w2h, g_w2h);
  cudaGetSymbolAddress((void**)&w3h, g_w3h);
  cudaGetSymbolAddress((void**)&weh, g_weh);

  constexpr int SMEM_T2 = 4*49152 + 1024;
  cudaFuncSetAttribute(tc_gemm<1,false,2>, cudaFuncAttributeMaxDynamicSharedMemorySize, SMEM_T2);
  cudaFuncSetAttribute(tc_gemm<0,true ,1>, cudaFuncAttributeMaxDynamicSharedMemorySize, SMEM_T2);
  cudaFuncSetAttribute(tc_gemm_big, cudaFuncAttributeMaxDynamicSharedMemorySize, SMEM_T2);

  cudaStream_t s2;
  cudaStreamCreateWithFlags(&s2, cudaStreamNonBlocking);
  cudaEvent_t eFork, eWts, eTrunk, eRoute;
  cudaEventCreateWithFlags(&eFork,  cudaEventDisableTiming);
  cudaEventCreateWithFlags(&eWts,   cudaEventDisableTiming);
  cudaEventCreateWithFlags(&eTrunk, cudaEventDisableTiming);
  cudaEventCreateWithFlags(&eRoute, cudaEventDisableTiming);

  dim3 blk(256);

  // ---- fork: expert-weight prep on s2, overlapped with trunk ----
  cudaEventRecord(eFork, 0);
  cudaStreamWaitEvent(s2, eFork, 0);
  tsp_k<<<dim3(32,32,16),blk,0,s2>>>(eW, weh, 1024, 1024);
  cudaEventRecord(eWts, s2);

  // ---- main: trunk weight prep + trunk GEMMs (fp16 2-term A) ----
  tsp_k<<<dim3(16, 4, 1),blk>>>(sW1, w1h, 128, 512);
  tsp_k<<<dim3(16,16, 1),blk>>>(sW2, w2h, 512, 512);
  tsp_k<<<dim3(32,16, 1),blk>>>(sW3, w3h, 512, 1024);
  cvt_split_k<<<1024,blk>>>(x, 192, 128, xoh, xol, 8192L*128);
  tc_gemm<1,false,2><<<dim3(4,64,1),blk,SMEM_T2>>>(
      xoh,xol,0,128, w1h,0, sb1,0, nullptr, h1h,h1l,0, 512,128);
  tc_gemm<1,false,2><<<dim3(4,64,1),blk,SMEM_T2>>>(
      h1h,h1l,0,512, w2h,0, sb2,0, nullptr, h2h,h2l,0, 512,512);
  tc_gemm<0,true,1><<<dim3(8,64,1),blk,SMEM_T2>>>(
      h2h,h2l,0,512, w3h,0, sb3,0, f, fh,nullptr,0, 1024,512);
  cudaEventRecord(eTrunk, 0);

  // ---- s2: routing chain (fma pipe), overlapped with expert L0 GEMM ----
  cudaStreamWaitEvent(s2, eTrunk, 0);
  gemm_k<128,128,2,false><<<dim3(8,64,1),blk,0,s2>>>(x+128,192,0, tW,0, tb,0, f, r,0, 8192,1024,64);
  gemm_k<64,64,0,true ><<<dim3(1,128,1),blk,0,s2>>>(r,1024,0, rdW,0, rdb,0, nullptr, p,0, 8192,64,1024);
  gemm_k<128,128,3,false><<<dim3(8,64,1),blk,0,s2>>>(p,64,0,
      ruW,0, rub,0, r, q,0, 8192,1024,64);
  gemm_k<64,64,0,false><<<dim3(1,128,1),blk,0,s2>>>(q,1024,0,
      rdW+1024L*64,0, rdb+64,0, nullptr, p+8192L*64,0, 8192,64,1024);
  softmax_k<<<(2*8192*8+255)/256,blk,0,s2>>>(p, pr, 2*8192*8);
  cudaEventRecord(eRoute, s2);

  // ---- main: expert layer 0 (fat-tile fp16 1-term, fp16 output) ----
  cudaStreamWaitEvent(0, eWts, 0);
  tc_gemm_big<<<dim3(8,32,8),blk,SMEM_T2>>>(
      fh,0,1024, weh,1048576, eb,1024, heh,8388608, 1024,1024);

  // ---- join: mixing needs routing probs ----
  cudaStreamWaitEvent(0, eRoute, 0);
  mix_k<<<8192,blk>>>(heh, pr, xxh);

  // expert layer 1 (fat-tile fp16 1-term, fp16 output)
  tc_gemm_big<<<dim3(8,32,8),blk,SMEM_T2>>>(
      xxh,8388608,1024, weh+8L*1048576,1048576, eb+8192,1024, heh,8388608, 1024,1024);

  // fused mix(layer1) + heads
  heads_mix_k<<<8192,blk>>>(heh, pr+8192*64, aW, ab, cW, cb, out);
}